// round 9
// baseline (speedup 1.0000x reference)
#include <cuda_runtime.h>
#include <cuda_bf16.h>
#include <cstdint>

// ---------------------------------------------------------------------------
// Problem constants
// ---------------------------------------------------------------------------
#define BATCH   4
#define N1      2048
#define N2      8192
#define C1      128
#define C2      64
#define KP      15
#define FOUT    128
#define NSAMP   16
#define NQ      (BATCH * N2)          // 32768 queries
#define KDIM    (KP * C1)             // 1920
#define OUTC    (FOUT + C2)           // 192
#define NCHUNK  (KDIM / 32)           // 60 K-chunks of 32 bf16 (64B rows)

#define GRID    8                     // 8x8x8 spatial bins
#define NCELL   (GRID * GRID * GRID)  // 512
#define CELLH   0.125f

// Scratch (device globals)
__device__ int            g_idx[NQ * NSAMP];
__device__ float4         g_sxyz[BATCH * N1];        // binned points (x,y,z,idx)
__device__ int            g_cellstart[BATCH * (NCELL + 1)];
__device__ __nv_bfloat16  g_a_hi[(size_t)NQ * KDIM];
__device__ __nv_bfloat16  g_a_lo[(size_t)NQ * KDIM];
__device__ __nv_bfloat16  g_b_hi[(size_t)FOUT * KDIM];
__device__ __nv_bfloat16  g_b_lo[(size_t)FOUT * KDIM];

// ---------------------------------------------------------------------------
// Helpers
// ---------------------------------------------------------------------------
__device__ __forceinline__ uint32_t smem_u32(const void* p) {
    uint32_t a;
    asm("{ .reg .u64 t; cvta.to.shared.u64 t, %1; cvt.u32.u64 %0, t; }"
        : "=r"(a) : "l"(p));
    return a;
}
__device__ __forceinline__ void ldsm4(uint32_t* r, uint32_t addr) {
    asm volatile("ldmatrix.sync.aligned.m8n8.x4.shared.b16 {%0,%1,%2,%3}, [%4];"
                 : "=r"(r[0]), "=r"(r[1]), "=r"(r[2]), "=r"(r[3]) : "r"(addr));
}
__device__ __forceinline__ void mma16816(float* c, const uint32_t* a,
                                         const uint32_t* b) {
    asm volatile(
        "mma.sync.aligned.m16n8k16.row.col.f32.bf16.bf16.f32 "
        "{%0,%1,%2,%3}, {%4,%5,%6,%7}, {%8,%9}, {%0,%1,%2,%3};"
        : "+f"(c[0]), "+f"(c[1]), "+f"(c[2]), "+f"(c[3])
        : "r"(a[0]), "r"(a[1]), "r"(a[2]), "r"(a[3]), "r"(b[0]), "r"(b[1]));
}
__device__ __forceinline__ int cellof(float x) {
    int c = (int)(x * (float)GRID);
    return min(GRID - 1, max(0, c));
}

// packed f32x2 (sm_100+ PTX, base family feature)
#define FFMA2(acc, a, b) \
    asm("fma.rn.f32x2 %0, %1, %2, %0;" : "+l"(acc) : "l"(a), "l"(b))
#define PACKF2(out, lo, hi) \
    asm("mov.b64 %0, {%1, %2};" : "=l"(out) : "f"(lo), "f"(hi))
#define UNPACKF2(lo, hi, in) \
    asm("mov.b64 {%0, %1}, %2;" : "=f"(lo), "=f"(hi) : "l"(in))
#define CVTBF2(res, hi, lo) \
    asm("cvt.rn.bf16x2.f32 %0, %1, %2;" : "=r"(res) : "f"(hi), "f"(lo))

// 64B-row smem swizzle: quad (16B) index XORed with ((row>>1)&3)
__device__ __forceinline__ uint32_t sw64(int row, int kb) {
    return row * 64 + (kb ^ (((row >> 1) & 3) << 4));
}

// ---------------------------------------------------------------------------
// Kernel 0: prep = spatial binning (blocks 0..3) + W split/transpose (4..483)
// ---------------------------------------------------------------------------
__global__ __launch_bounds__(512) void prep_kernel(
    const float* __restrict__ xyz1, const float* __restrict__ W)
{
    const int t = threadIdx.x;

    if (blockIdx.x >= BATCH) {
        const int i = (blockIdx.x - BATCH) * 512 + t;
        const int kc = i / FOUT;
        const int f  = i % FOUT;
        float w = W[i];
        __nv_bfloat16 h = __float2bfloat16(w);
        g_b_hi[(size_t)f * KDIM + kc] = h;
        g_b_lo[(size_t)f * KDIM + kc] = __float2bfloat16(w - __bfloat162float(h));
        return;
    }

    __shared__ int cnt[NCELL];
    __shared__ int sscan[NCELL];
    __shared__ int cursor[NCELL];

    const int b = blockIdx.x;
    cnt[t] = 0;
    __syncthreads();

    float px[N1 / 512], py[N1 / 512], pz[N1 / 512];
    int   cl[N1 / 512];
    #pragma unroll
    for (int k = 0; k < N1 / 512; ++k) {
        const int i = t + k * 512;
        px[k] = xyz1[((size_t)b * N1 + i) * 3 + 0];
        py[k] = xyz1[((size_t)b * N1 + i) * 3 + 1];
        pz[k] = xyz1[((size_t)b * N1 + i) * 3 + 2];
        cl[k] = (cellof(pz[k]) << 6) | (cellof(py[k]) << 3) | cellof(px[k]);
        atomicAdd(&cnt[cl[k]], 1);
    }
    __syncthreads();

    sscan[t] = cnt[t];
    __syncthreads();
    #pragma unroll
    for (int off = 1; off < NCELL; off <<= 1) {
        int add = (t >= off) ? sscan[t - off] : 0;
        __syncthreads();
        sscan[t] += add;
        __syncthreads();
    }
    const int excl = sscan[t] - cnt[t];
    g_cellstart[b * (NCELL + 1) + t] = excl;
    if (t == NCELL - 1) g_cellstart[b * (NCELL + 1) + NCELL] = N1;
    cursor[t] = excl;
    __syncthreads();

    #pragma unroll
    for (int k = 0; k < N1 / 512; ++k) {
        const int i = t + k * 512;
        const int pos = atomicAdd(&cursor[cl[k]], 1);
        g_sxyz[b * N1 + pos] = make_float4(px[k], py[k], pz[k], __int_as_float(i));
    }
}

// ---------------------------------------------------------------------------
// Kernel 1: kNN via expanding Chebyshev shells over the bin grid.
// ---------------------------------------------------------------------------
__global__ __launch_bounds__(256) void knn_kernel(const float* __restrict__ xyz2)
{
    __shared__ float4 spt[N1];            // 32KB
    __shared__ int    cst[NCELL + 1];

    const int b = blockIdx.y;
    for (int i = threadIdx.x; i < N1; i += 256)
        spt[i] = g_sxyz[b * N1 + i];
    for (int i = threadIdx.x; i < NCELL + 1; i += 256)
        cst[i] = g_cellstart[b * (NCELL + 1) + i];
    __syncthreads();

    const int q = b * N2 + blockIdx.x * 256 + threadIdx.x;
    const float qx = xyz2[q * 3 + 0];
    const float qy = xyz2[q * 3 + 1];
    const float qz = xyz2[q * 3 + 2];
    const int cx = cellof(qx), cy = cellof(qy), cz = cellof(qz);

    float dk[NSAMP];
    int   ik[NSAMP];
    #pragma unroll
    for (int p = 0; p < NSAMP; ++p) { dk[p] = 3.4e38f; ik[p] = 0; }

    for (int R = 0; R < GRID; ++R) {
        const int zlo = max(cz - R, 0), zhi = min(cz + R, GRID - 1);
        const int ylo = max(cy - R, 0), yhi = min(cy + R, GRID - 1);
        const int xlo = max(cx - R, 0), xhi = min(cx + R, GRID - 1);
        for (int z = zlo; z <= zhi; ++z) {
            const int az = abs(z - cz);
            for (int y = ylo; y <= yhi; ++y) {
                const int ay = abs(y - cy);
                for (int x = xlo; x <= xhi; ++x) {
                    const int ax = abs(x - cx);
                    if (max(max(az, ay), ax) != R) continue;  // shell only
                    const int cell = (z << 6) | (y << 3) | x;
                    const int e = cst[cell + 1];
                    for (int p = cst[cell]; p < e; ++p) {
                        const float4 P = spt[p];
                        const float dx = qx - P.x;
                        const float dy = qy - P.y;
                        const float dz = qz - P.z;
                        const float d2 = fmaf(dx, dx, fmaf(dy, dy, dz * dz));
                        if (d2 < dk[NSAMP - 1]) {
                            dk[NSAMP - 1] = d2;
                            ik[NSAMP - 1] = __float_as_int(P.w);
                            #pragma unroll
                            for (int s = NSAMP - 1; s > 0; --s) {
                                if (dk[s] < dk[s - 1]) {
                                    float td = dk[s]; dk[s] = dk[s-1]; dk[s-1] = td;
                                    int   ti = ik[s]; ik[s] = ik[s-1]; ik[s-1] = ti;
                                }
                            }
                        }
                    }
                }
            }
        }
        const float bnd = (float)R * CELLH;
        if (dk[NSAMP - 1] < bnd * bnd) break;
    }

    int* o = g_idx + q * NSAMP;
    #pragma unroll
    for (int p = 0; p < NSAMP; ++p) o[p] = ik[p];
}

// ---------------------------------------------------------------------------
// Kernel 2: weighted aggregation with packed f32x2 FMA (unchanged).
// ---------------------------------------------------------------------------
__global__ __launch_bounds__(128) void wf_kernel(
    const float* __restrict__ xyz1, const float* __restrict__ feat1,
    const float* __restrict__ xyz2, const float* __restrict__ kp)
{
    const int wid = threadIdx.x >> 5;
    const int L   = threadIdx.x & 31;
    const int q   = blockIdx.x * 4 + wid;
    const int b   = q >> 13;

    __shared__ float  skp[KP * 3];
    __shared__ float2 sw2[4][NSAMP][KP];

    if (threadIdx.x < KP * 3) skp[threadIdx.x] = kp[threadIdx.x];
    __syncthreads();

    int sid = 0;
    if (L < NSAMP) {
        sid = g_idx[q * NSAMP + L];
        const float rx = xyz1[((size_t)b * N1 + sid) * 3 + 0] - xyz2[q * 3 + 0];
        const float ry = xyz1[((size_t)b * N1 + sid) * 3 + 1] - xyz2[q * 3 + 1];
        const float rz = xyz1[((size_t)b * N1 + sid) * 3 + 2] - xyz2[q * 3 + 2];
        #pragma unroll
        for (int k = 0; k < KP; ++k) {
            float dx = rx - skp[k * 3 + 0];
            float dy = ry - skp[k * 3 + 1];
            float dz = rz - skp[k * 3 + 2];
            float sq = dx * dx + dy * dy + dz * dz;
            float dist = sqrtf(fmaxf(sq, 1e-12f));
            float wt = fmaxf(0.0f, 1.0f - dist / 0.2f);
            sw2[wid][L][k] = make_float2(wt, wt);
        }
    }
    __syncwarp();

    const float* fb = feat1 + (size_t)b * N1 * C1;
    unsigned long long fxy[NSAMP], fzw[NSAMP];
    #pragma unroll
    for (int s = 0; s < NSAMP; ++s) {
        const int is = __shfl_sync(0xffffffffu, sid, s);
        const float4 v = *(const float4*)(fb + (size_t)is * C1 + 4 * L);
        PACKF2(fxy[s], v.x, v.y);
        PACKF2(fzw[s], v.z, v.w);
    }

    unsigned long long a0[KP], a1[KP];
    #pragma unroll
    for (int k = 0; k < KP; ++k) { a0[k] = 0ull; a1[k] = 0ull; }

    #pragma unroll
    for (int s = 0; s < NSAMP; ++s) {
        #pragma unroll
        for (int k = 0; k < KP; ++k) {
            const unsigned long long wp =
                *(const unsigned long long*)&sw2[wid][s][k];
            FFMA2(a0[k], wp, fxy[s]);
            FFMA2(a1[k], wp, fzw[s]);
        }
    }

    const size_t qbase = (size_t)q * KDIM + 4 * L;
    #pragma unroll
    for (int k = 0; k < KP; ++k) {
        float vx, vy, vz, vw;
        UNPACKF2(vx, vy, a0[k]);
        UNPACKF2(vz, vw, a1[k]);
        uint32_t h0, h1;
        CVTBF2(h0, vy, vx);
        CVTBF2(h1, vw, vz);
        float hx = __uint_as_float(h0 << 16);
        float hy = __uint_as_float(h0 & 0xFFFF0000u);
        float hz = __uint_as_float(h1 << 16);
        float hw = __uint_as_float(h1 & 0xFFFF0000u);
        uint32_t l0, l1;
        CVTBF2(l0, vy - hy, vx - hx);
        CVTBF2(l1, vw - hw, vz - hz);
        uint2 hi; hi.x = h0; hi.y = h1;
        uint2 lo; lo.x = l0; lo.y = l1;
        *(uint2*)(g_a_hi + qbase + k * C1) = hi;
        *(uint2*)(g_a_lo + qbase + k * C1) = lo;
    }
}

// ---------------------------------------------------------------------------
// Kernel 3: mma.sync bf16 GEMM (2-way split, 3 products), fused concat.
// M=32768 (128 CTAs of 256 rows), N=128, K=1920 in 60 chunks of 32 (64B rows).
// 512 threads = 16 warps in 4(M)x4(N): warp tile 64x32 -> 4 warps/SMSP.
// 4-stage cp.async pipeline (48KB/stage), one __syncthreads per chunk.
// ---------------------------------------------------------------------------
#define A_SUB       16384               // 256 rows x 64B
#define B_SUB       8192                // 128 rows x 64B
#define STAGE_BYTES (2 * A_SUB + 2 * B_SUB)   // 48KB
#define NSTAGE      4
#define GEMM_SMEM   (NSTAGE * STAGE_BYTES)    // 192KB

__global__ __launch_bounds__(512, 1)
void gemm_kernel(const float* __restrict__ feat2, float* __restrict__ out)
{
    extern __shared__ __align__(1024) char dsmem[];

    const int tid = threadIdx.x;
    const int wid = tid >> 5;
    const int L   = tid & 31;
    const int m0  = blockIdx.x * 256;
    const int wm  = wid & 3;              // 0..3 (M, 64 rows each)
    const int wn  = wid >> 2;             // 0..3 (N, 32 cols each)

    const uint32_t base = smem_u32(dsmem);

    const char* srcA_hi = (const char*)g_a_hi + (size_t)m0 * (KDIM * 2);
    const char* srcA_lo = (const char*)g_a_lo + (size_t)m0 * (KDIM * 2);
    const char* srcB_hi = (const char*)g_b_hi;
    const char* srcB_lo = (const char*)g_b_lo;

    // one stage: A hi/lo 256 rows x 4 quads (1024), B hi/lo 128 rows x 4 (512)
    auto load_stage = [&](int chunk, int buf) {
        const uint32_t sbase = base + buf * STAGE_BYTES;
        #pragma unroll
        for (int arr = 0; arr < 2; ++arr) {
            const char* s = arr ? srcA_lo : srcA_hi;
            const uint32_t so = sbase + arr * A_SUB;
            #pragma unroll
            for (int v = 0; v < 2; ++v) {
                int idx = v * 512 + tid;          // 0..1023
                int row = idx >> 2;               // 0..255
                int kb  = (idx & 3) << 4;         // 0..48
                const char* g = s + (size_t)row * (KDIM * 2) + chunk * 64 + kb;
                uint32_t sa = so + sw64(row, kb);
                asm volatile("cp.async.cg.shared.global [%0], [%1], 16;"
                             :: "r"(sa), "l"(g));
            }
        }
        #pragma unroll
        for (int arr = 0; arr < 2; ++arr) {
            const char* s = arr ? srcB_lo : srcB_hi;
            const uint32_t so = sbase + 2 * A_SUB + arr * B_SUB;
            {
                int idx = tid;                    // 0..511
                int row = idx >> 2;               // 0..127
                int kb  = (idx & 3) << 4;
                const char* g = s + (size_t)row * (KDIM * 2) + chunk * 64 + kb;
                uint32_t sa = so + sw64(row, kb);
                asm volatile("cp.async.cg.shared.global [%0], [%1], 16;"
                             :: "r"(sa), "l"(g));
            }
        }
        asm volatile("cp.async.commit_group;" ::: "memory");
    };

    // ldmatrix per-thread offsets (64B rows, quad swizzle)
    int aRow = wm * 64 + (L & 15);                  // + mt*16
    int aKb  = (L >> 4) * 16;                       // 0 or 16
    int bRow = wn * 32 + ((L >> 4) << 3) + (L & 7); // + ng*16
    int bKb  = ((L >> 3) & 1) * 16;

    uint32_t aOff[4], aXor[4];
    #pragma unroll
    for (int mt = 0; mt < 4; ++mt) {
        int r = aRow + mt * 16;
        aOff[mt] = r * 64;
        aXor[mt] = ((r >> 1) & 3) << 4;
    }
    uint32_t bOff[2], bXor[2];
    #pragma unroll
    for (int ng = 0; ng < 2; ++ng) {
        int r = bRow + ng * 16;
        bOff[ng] = r * 64;
        bXor[ng] = ((r >> 1) & 3) << 4;
    }

    float acc[4][4][4];
    #pragma unroll
    for (int i = 0; i < 4; ++i)
        #pragma unroll
        for (int j = 0; j < 4; ++j)
            #pragma unroll
            for (int k = 0; k < 4; ++k) acc[i][j][k] = 0.0f;

    load_stage(0, 0);
    load_stage(1, 1);
    load_stage(2, 2);

    // fused concat: copy feat2 rows [m0, m0+256) into out[:,128:192)
    {
        const float* f2 = feat2 + (size_t)m0 * C2;
        float* o2 = out + (size_t)m0 * OUTC + FOUT;
        #pragma unroll
        for (int i = 0; i < 8; ++i) {
            int v = i * 512 + tid;            // 0..4095
            int row = v >> 4;
            int j   = v & 15;
            float4 t = *(const float4*)(f2 + (size_t)row * C2 + j * 4);
            *(float4*)(o2 + (size_t)row * OUTC + j * 4) = t;
        }
    }

    for (int i = 0; i < NCHUNK; ++i) {
        const int buf = i & 3;
        if (i + 2 < NCHUNK)
            asm volatile("cp.async.wait_group 2;" ::: "memory");
        else if (i + 1 < NCHUNK)
            asm volatile("cp.async.wait_group 1;" ::: "memory");
        else
            asm volatile("cp.async.wait_group 0;" ::: "memory");
        __syncthreads();   // all warps done with buf (i-1)&3 AND buf i ready

        const uint32_t sb  = base + buf * STAGE_BYTES;
        const uint32_t sAh = sb;
        const uint32_t sAl = sb + A_SUB;
        const uint32_t sBh = sb + 2 * A_SUB;
        const uint32_t sBl = sb + 2 * A_SUB + B_SUB;

        #pragma unroll
        for (int ks = 0; ks < 2; ++ks) {
            const uint32_t kA = ks * 32 + aKb;
            const uint32_t kB = ks * 32 + bKb;
            uint32_t ah[4][4], al[4][4];
            #pragma unroll
            for (int mt = 0; mt < 4; ++mt) {
                uint32_t o = aOff[mt] + (kA ^ aXor[mt]);
                ldsm4(ah[mt], sAh + o);
                ldsm4(al[mt], sAl + o);
            }
            #pragma unroll
            for (int ng = 0; ng < 2; ++ng) {
                uint32_t bh[4], bl[4];
                uint32_t o = bOff[ng] + (kB ^ bXor[ng]);
                ldsm4(bh, sBh + o);
                ldsm4(bl, sBl + o);
                #pragma unroll
                for (int mt = 0; mt < 4; ++mt) {
                    #pragma unroll
                    for (int h = 0; h < 2; ++h) {
                        float* c = acc[mt][ng * 2 + h];
                        const uint32_t* fh = &bh[h * 2];
                        const uint32_t* fl = &bl[h * 2];
                        mma16816(c, ah[mt], fh);   // hi*hi
                        mma16816(c, ah[mt], fl);   // hi*lo
                        mma16816(c, al[mt], fh);   // lo*hi
                    }
                }
            }
        }

        if (i + 3 < NCHUNK) load_stage(i + 3, (i + 3) & 3);
    }

    #pragma unroll
    for (int mt = 0; mt < 4; ++mt) {
        #pragma unroll
        for (int nt = 0; nt < 4; ++nt) {
            const float* c = acc[mt][nt];
            int row = m0 + wm * 64 + mt * 16 + (L >> 2);
            int col = wn * 32 + nt * 8 + (L & 3) * 2;
            float2 v0, v1;
            v0.x = fmaxf(c[0], 0.0f); v0.y = fmaxf(c[1], 0.0f);
            v1.x = fmaxf(c[2], 0.0f); v1.y = fmaxf(c[3], 0.0f);
            *(float2*)(out + (size_t)row * OUTC + col)       = v0;
            *(float2*)(out + (size_t)(row + 8) * OUTC + col) = v1;
        }
    }
}

// ---------------------------------------------------------------------------
// Launch
// ---------------------------------------------------------------------------
extern "C" void kernel_launch(void* const* d_in, const int* in_sizes, int n_in,
                              void* d_out, int out_size)
{
    const float* xyz1  = (const float*)d_in[0];
    const float* feat1 = (const float*)d_in[1];
    const float* xyz2  = (const float*)d_in[2];
    const float* feat2 = (const float*)d_in[3];
    const float* kp    = (const float*)d_in[4];
    const float* W     = (const float*)d_in[5];
    float* out = (float*)d_out;

    cudaFuncSetAttribute(gemm_kernel,
                         cudaFuncAttributeMaxDynamicSharedMemorySize, GEMM_SMEM);

    prep_kernel<<<BATCH + (KDIM * FOUT) / 512, 512>>>(xyz1, W);
    knn_kernel<<<dim3(N2 / 256, BATCH), 256>>>(xyz2);
    wf_kernel<<<NQ / 4, 128>>>(xyz1, feat1, xyz2, kp);
    gemm_kernel<<<NQ / 256, 512, GEMM_SMEM>>>(feat2, out);
}

// round 10
// speedup vs baseline: 1.2107x; 1.2107x over previous
#include <cuda_runtime.h>
#include <cuda_fp16.h>
#include <cstdint>

// ---------------------------------------------------------------------------
// Problem constants
// ---------------------------------------------------------------------------
#define BATCH   4
#define N1      2048
#define N2      8192
#define C1      128
#define C2      64
#define KP      15
#define FOUT    128
#define NSAMP   16
#define NQ      (BATCH * N2)          // 32768 queries
#define KDIM    (KP * C1)             // 1920
#define OUTC    (FOUT + C2)           // 192
#define NCHUNK  (KDIM / 32)           // 60 K-chunks of 32 fp16 (64B rows)

#define GRID    8                     // 8x8x8 spatial bins
#define NCELL   (GRID * GRID * GRID)  // 512
#define CELLH   0.125f

// Scratch (device globals)
__device__ int     g_idx[NQ * NSAMP];
__device__ float4  g_sxyz[BATCH * N1];        // binned points (x,y,z,idx)
__device__ int     g_cellstart[BATCH * (NCELL + 1)];
__device__ __half  g_a[(size_t)NQ * KDIM];    // wf in fp16, row-major (q, kc)
__device__ __half  g_b_hi[(size_t)FOUT * KDIM];  // W^T split, (f, kc)
__device__ __half  g_b_lo[(size_t)FOUT * KDIM];

// ---------------------------------------------------------------------------
// Helpers
// ---------------------------------------------------------------------------
__device__ __forceinline__ uint32_t smem_u32(const void* p) {
    uint32_t a;
    asm("{ .reg .u64 t; cvta.to.shared.u64 t, %1; cvt.u32.u64 %0, t; }"
        : "=r"(a) : "l"(p));
    return a;
}
__device__ __forceinline__ void ldsm4(uint32_t* r, uint32_t addr) {
    asm volatile("ldmatrix.sync.aligned.m8n8.x4.shared.b16 {%0,%1,%2,%3}, [%4];"
                 : "=r"(r[0]), "=r"(r[1]), "=r"(r[2]), "=r"(r[3]) : "r"(addr));
}
__device__ __forceinline__ void mma16816h(float* c, const uint32_t* a,
                                          const uint32_t* b) {
    asm volatile(
        "mma.sync.aligned.m16n8k16.row.col.f32.f16.f16.f32 "
        "{%0,%1,%2,%3}, {%4,%5,%6,%7}, {%8,%9}, {%0,%1,%2,%3};"
        : "+f"(c[0]), "+f"(c[1]), "+f"(c[2]), "+f"(c[3])
        : "r"(a[0]), "r"(a[1]), "r"(a[2]), "r"(a[3]), "r"(b[0]), "r"(b[1]));
}
__device__ __forceinline__ int cellof(float x) {
    int c = (int)(x * (float)GRID);
    return min(GRID - 1, max(0, c));
}

// packed f32x2 (sm_100+ PTX, base family feature)
#define FFMA2(acc, a, b) \
    asm("fma.rn.f32x2 %0, %1, %2, %0;" : "+l"(acc) : "l"(a), "l"(b))
#define PACKF2(out, lo, hi) \
    asm("mov.b64 %0, {%1, %2};" : "=l"(out) : "f"(lo), "f"(hi))
#define UNPACKF2(lo, hi, in) \
    asm("mov.b64 {%0, %1}, %2;" : "=f"(lo), "=f"(hi) : "l"(in))

// 64B-row smem swizzle: quad (16B) index XORed with ((row>>1)&3)
__device__ __forceinline__ uint32_t sw64(int row, int kb) {
    return row * 64 + (kb ^ (((row >> 1) & 3) << 4));
}

// ---------------------------------------------------------------------------
// Kernel 0: prep = spatial binning (blocks 0..3) + W split/transpose (4..483)
// ---------------------------------------------------------------------------
__global__ __launch_bounds__(512) void prep_kernel(
    const float* __restrict__ xyz1, const float* __restrict__ W)
{
    const int t = threadIdx.x;

    if (blockIdx.x >= BATCH) {
        const int i = (blockIdx.x - BATCH) * 512 + t;
        const int kc = i / FOUT;
        const int f  = i % FOUT;
        float w = W[i];
        __half h = __float2half_rn(w);
        g_b_hi[(size_t)f * KDIM + kc] = h;
        g_b_lo[(size_t)f * KDIM + kc] = __float2half_rn(w - __half2float(h));
        return;
    }

    __shared__ int cnt[NCELL];
    __shared__ int sscan[NCELL];
    __shared__ int cursor[NCELL];

    const int b = blockIdx.x;
    cnt[t] = 0;
    __syncthreads();

    float px[N1 / 512], py[N1 / 512], pz[N1 / 512];
    int   cl[N1 / 512];
    #pragma unroll
    for (int k = 0; k < N1 / 512; ++k) {
        const int i = t + k * 512;
        px[k] = xyz1[((size_t)b * N1 + i) * 3 + 0];
        py[k] = xyz1[((size_t)b * N1 + i) * 3 + 1];
        pz[k] = xyz1[((size_t)b * N1 + i) * 3 + 2];
        cl[k] = (cellof(pz[k]) << 6) | (cellof(py[k]) << 3) | cellof(px[k]);
        atomicAdd(&cnt[cl[k]], 1);
    }
    __syncthreads();

    sscan[t] = cnt[t];
    __syncthreads();
    #pragma unroll
    for (int off = 1; off < NCELL; off <<= 1) {
        int add = (t >= off) ? sscan[t - off] : 0;
        __syncthreads();
        sscan[t] += add;
        __syncthreads();
    }
    const int excl = sscan[t] - cnt[t];
    g_cellstart[b * (NCELL + 1) + t] = excl;
    if (t == NCELL - 1) g_cellstart[b * (NCELL + 1) + NCELL] = N1;
    cursor[t] = excl;
    __syncthreads();

    #pragma unroll
    for (int k = 0; k < N1 / 512; ++k) {
        const int i = t + k * 512;
        const int pos = atomicAdd(&cursor[cl[k]], 1);
        g_sxyz[b * N1 + pos] = make_float4(px[k], py[k], pz[k], __int_as_float(i));
    }
}

// ---------------------------------------------------------------------------
// Kernel 1: kNN via expanding Chebyshev shells, contiguous row-run scans.
// For each (z,y) row of a shell, the x-cells form 1 (or 2) contiguous point
// ranges in the sorted array -> single scan, no per-cell loop/test.
// ---------------------------------------------------------------------------
__global__ __launch_bounds__(256) void knn_kernel(const float* __restrict__ xyz2)
{
    __shared__ float4 spt[N1];            // 32KB
    __shared__ int    cst[NCELL + 1];

    const int b = blockIdx.y;
    for (int i = threadIdx.x; i < N1; i += 256)
        spt[i] = g_sxyz[b * N1 + i];
    for (int i = threadIdx.x; i < NCELL + 1; i += 256)
        cst[i] = g_cellstart[b * (NCELL + 1) + i];
    __syncthreads();

    const int q = b * N2 + blockIdx.x * 256 + threadIdx.x;
    const float qx = xyz2[q * 3 + 0];
    const float qy = xyz2[q * 3 + 1];
    const float qz = xyz2[q * 3 + 2];
    const int cx = cellof(qx), cy = cellof(qy), cz = cellof(qz);

    float dk[NSAMP];
    int   ik[NSAMP];
    #pragma unroll
    for (int p = 0; p < NSAMP; ++p) { dk[p] = 3.4e38f; ik[p] = 0; }

    auto scan_run = [&](int rowbase, int xa, int xb) {
        const int pe = cst[rowbase + xb + 1];
        for (int p = cst[rowbase + xa]; p < pe; ++p) {
            const float4 P = spt[p];
            const float dx = qx - P.x;
            const float dy = qy - P.y;
            const float dz = qz - P.z;
            const float d2 = fmaf(dx, dx, fmaf(dy, dy, dz * dz));
            if (d2 < dk[NSAMP - 1]) {
                dk[NSAMP - 1] = d2;
                ik[NSAMP - 1] = __float_as_int(P.w);
                #pragma unroll
                for (int s = NSAMP - 1; s > 0; --s) {
                    if (dk[s] < dk[s - 1]) {
                        float td = dk[s]; dk[s] = dk[s-1]; dk[s-1] = td;
                        int   ti = ik[s]; ik[s] = ik[s-1]; ik[s-1] = ti;
                    }
                }
            }
        }
    };

    for (int R = 0; R < GRID; ++R) {
        const int zlo = max(cz - R, 0), zhi = min(cz + R, GRID - 1);
        const int ylo = max(cy - R, 0), yhi = min(cy + R, GRID - 1);
        const int xlo = max(cx - R, 0), xhi = min(cx + R, GRID - 1);
        for (int z = zlo; z <= zhi; ++z) {
            const int az = abs(z - cz);
            for (int y = ylo; y <= yhi; ++y) {
                const int ay = abs(y - cy);
                const int rowbase = (z << 6) | (y << 3);
                if (az == R || ay == R) {
                    scan_run(rowbase, xlo, xhi);       // full row in shell
                } else {
                    if (cx - R >= 0)        scan_run(rowbase, cx - R, cx - R);
                    if (cx + R <= GRID - 1) scan_run(rowbase, cx + R, cx + R);
                }
            }
        }
        const float bnd = (float)R * CELLH;
        if (dk[NSAMP - 1] < bnd * bnd) break;
    }

    int* o = g_idx + q * NSAMP;
    #pragma unroll
    for (int p = 0; p < NSAMP; ++p) o[p] = ik[p];
}

// ---------------------------------------------------------------------------
// Kernel 2: weighted aggregation, fp16 output (single array).
// One warp per query; lane owns 4 channels; packed f32x2 FMA.
// ---------------------------------------------------------------------------
__global__ __launch_bounds__(128) void wf_kernel(
    const float* __restrict__ xyz1, const float* __restrict__ feat1,
    const float* __restrict__ xyz2, const float* __restrict__ kp)
{
    const int wid = threadIdx.x >> 5;
    const int L   = threadIdx.x & 31;
    const int q   = blockIdx.x * 4 + wid;
    const int b   = q >> 13;

    __shared__ float  skp[KP * 3];
    __shared__ float2 sw2[4][NSAMP][KP];

    if (threadIdx.x < KP * 3) skp[threadIdx.x] = kp[threadIdx.x];
    __syncthreads();

    int sid = 0;
    if (L < NSAMP) {
        sid = g_idx[q * NSAMP + L];
        const float rx = xyz1[((size_t)b * N1 + sid) * 3 + 0] - xyz2[q * 3 + 0];
        const float ry = xyz1[((size_t)b * N1 + sid) * 3 + 1] - xyz2[q * 3 + 1];
        const float rz = xyz1[((size_t)b * N1 + sid) * 3 + 2] - xyz2[q * 3 + 2];
        #pragma unroll
        for (int k = 0; k < KP; ++k) {
            float dx = rx - skp[k * 3 + 0];
            float dy = ry - skp[k * 3 + 1];
            float dz = rz - skp[k * 3 + 2];
            float sq = dx * dx + dy * dy + dz * dz;
            float dist = sqrtf(fmaxf(sq, 1e-12f));
            float wt = fmaxf(0.0f, 1.0f - dist / 0.2f);
            sw2[wid][L][k] = make_float2(wt, wt);
        }
    }
    __syncwarp();

    const float* fb = feat1 + (size_t)b * N1 * C1;
    unsigned long long fxy[NSAMP], fzw[NSAMP];
    #pragma unroll
    for (int s = 0; s < NSAMP; ++s) {
        const int is = __shfl_sync(0xffffffffu, sid, s);
        const float4 v = *(const float4*)(fb + (size_t)is * C1 + 4 * L);
        PACKF2(fxy[s], v.x, v.y);
        PACKF2(fzw[s], v.z, v.w);
    }

    unsigned long long a0[KP], a1[KP];
    #pragma unroll
    for (int k = 0; k < KP; ++k) { a0[k] = 0ull; a1[k] = 0ull; }

    #pragma unroll
    for (int s = 0; s < NSAMP; ++s) {
        #pragma unroll
        for (int k = 0; k < KP; ++k) {
            const unsigned long long wp =
                *(const unsigned long long*)&sw2[wid][s][k];
            FFMA2(a0[k], wp, fxy[s]);
            FFMA2(a1[k], wp, fzw[s]);
        }
    }

    const size_t qbase = (size_t)q * KDIM + 4 * L;
    #pragma unroll
    for (int k = 0; k < KP; ++k) {
        float vx, vy, vz, vw;
        UNPACKF2(vx, vy, a0[k]);
        UNPACKF2(vz, vw, a1[k]);
        __half2 h0 = __floats2half2_rn(vx, vy);
        __half2 h1 = __floats2half2_rn(vz, vw);
        uint2 st;
        st.x = *(const uint32_t*)&h0;
        st.y = *(const uint32_t*)&h1;
        *(uint2*)(g_a + qbase + k * C1) = st;
    }
}

// ---------------------------------------------------------------------------
// Kernel 3: mma.sync fp16 GEMM, 2 products (A * (B_hi + B_lo)), fused concat.
// M=32768 (128 CTAs of 256 rows), N=128, K=1920 in 60 chunks of 32 (64B rows).
// 8 warps in 4(M)x2(N): warp tile 64x64. 4-stage cp.async (32KB/stage).
// ---------------------------------------------------------------------------
#define A_SUB       16384               // 256 rows x 64B
#define B_SUB       8192                // 128 rows x 64B
#define STAGE_BYTES (A_SUB + 2 * B_SUB)       // 32KB
#define NSTAGE      4
#define GEMM_SMEM   (NSTAGE * STAGE_BYTES)    // 128KB

__global__ __launch_bounds__(256, 1)
void gemm_kernel(const float* __restrict__ feat2, float* __restrict__ out)
{
    extern __shared__ __align__(1024) char dsmem[];

    const int tid = threadIdx.x;
    const int wid = tid >> 5;
    const int L   = tid & 31;
    const int m0  = blockIdx.x * 256;
    const int wm  = wid & 3;              // 0..3 (M, 64 rows each)
    const int wn  = wid >> 2;             // 0..1 (N, 64 cols each)

    const uint32_t base = smem_u32(dsmem);

    const char* srcA  = (const char*)g_a + (size_t)m0 * (KDIM * 2);
    const char* srcBh = (const char*)g_b_hi;
    const char* srcBl = (const char*)g_b_lo;

    // one stage: A 256 rows x 4 quads (1024), B hi/lo 128 rows x 4 (512 each)
    auto load_stage = [&](int chunk, int buf) {
        const uint32_t sbase = base + buf * STAGE_BYTES;
        #pragma unroll
        for (int v = 0; v < 4; ++v) {
            int idx = v * 256 + tid;          // 0..1023
            int row = idx >> 2;               // 0..255
            int kb  = (idx & 3) << 4;         // 0..48
            const char* g = srcA + (size_t)row * (KDIM * 2) + chunk * 64 + kb;
            uint32_t sa = sbase + sw64(row, kb);
            asm volatile("cp.async.cg.shared.global [%0], [%1], 16;"
                         :: "r"(sa), "l"(g));
        }
        #pragma unroll
        for (int arr = 0; arr < 2; ++arr) {
            const char* s = arr ? srcBl : srcBh;
            const uint32_t so = sbase + A_SUB + arr * B_SUB;
            #pragma unroll
            for (int v = 0; v < 2; ++v) {
                int idx = v * 256 + tid;          // 0..511
                int row = idx >> 2;               // 0..127
                int kb  = (idx & 3) << 4;
                const char* g = s + (size_t)row * (KDIM * 2) + chunk * 64 + kb;
                uint32_t sa = so + sw64(row, kb);
                asm volatile("cp.async.cg.shared.global [%0], [%1], 16;"
                             :: "r"(sa), "l"(g));
            }
        }
        asm volatile("cp.async.commit_group;" ::: "memory");
    };

    // ldmatrix per-thread offsets (64B rows, quad swizzle)
    int aRow = wm * 64 + (L & 15);                  // + mt*16
    int aKb  = (L >> 4) * 16;                       // 0 or 16
    int bRow = wn * 64 + ((L >> 4) << 3) + (L & 7); // + ng*16
    int bKb  = ((L >> 3) & 1) * 16;

    uint32_t aOff[4], aXor[4];
    #pragma unroll
    for (int mt = 0; mt < 4; ++mt) {
        int r = aRow + mt * 16;
        aOff[mt] = r * 64;
        aXor[mt] = ((r >> 1) & 3) << 4;
    }
    uint32_t bOff[4], bXor[4];
    #pragma unroll
    for (int ng = 0; ng < 4; ++ng) {
        int r = bRow + ng * 16;
        bOff[ng] = r * 64;
        bXor[ng] = ((r >> 1) & 3) << 4;
    }

    float acc[4][8][4];
    #pragma unroll
    for (int i = 0; i < 4; ++i)
        #pragma unroll
        for (int j = 0; j < 8; ++j)
            #pragma unroll
            for (int k = 0; k < 4; ++k) acc[i][j][k] = 0.0f;

    load_stage(0, 0);
    load_stage(1, 1);
    load_stage(2, 2);

    // fused concat: copy feat2 rows [m0, m0+256) into out[:,128:192)
    {
        const float* f2 = feat2 + (size_t)m0 * C2;
        float* o2 = out + (size_t)m0 * OUTC + FOUT;
        #pragma unroll
        for (int i = 0; i < 16; ++i) {
            int v = i * 256 + tid;            // 0..4095
            int row = v >> 4;
            int j   = v & 15;
            float4 t = *(const float4*)(f2 + (size_t)row * C2 + j * 4);
            *(float4*)(o2 + (size_t)row * OUTC + j * 4) = t;
        }
    }

    for (int i = 0; i < NCHUNK; ++i) {
        const int buf = i & 3;
        if (i + 2 < NCHUNK)
            asm volatile("cp.async.wait_group 2;" ::: "memory");
        else if (i + 1 < NCHUNK)
            asm volatile("cp.async.wait_group 1;" ::: "memory");
        else
            asm volatile("cp.async.wait_group 0;" ::: "memory");
        __syncthreads();

        const uint32_t sb  = base + buf * STAGE_BYTES;
        const uint32_t sA  = sb;
        const uint32_t sBh = sb + A_SUB;
        const uint32_t sBl = sb + A_SUB + B_SUB;

        #pragma unroll
        for (int ks = 0; ks < 2; ++ks) {
            const uint32_t kA = ks * 32 + aKb;
            const uint32_t kB = ks * 32 + bKb;
            uint32_t a[4][4];
            #pragma unroll
            for (int mt = 0; mt < 4; ++mt)
                ldsm4(a[mt], sA + aOff[mt] + (kA ^ aXor[mt]));
            #pragma unroll
            for (int ng = 0; ng < 4; ++ng) {
                uint32_t bh[4], bl[4];
                uint32_t o = bOff[ng] + (kB ^ bXor[ng]);
                ldsm4(bh, sBh + o);
                ldsm4(bl, sBl + o);
                #pragma unroll
                for (int mt = 0; mt < 4; ++mt) {
                    #pragma unroll
                    for (int h = 0; h < 2; ++h) {
                        float* c = acc[mt][ng * 2 + h];
                        mma16816h(c, a[mt], &bh[h * 2]);   // a * b_hi
                        mma16816h(c, a[mt], &bl[h * 2]);   // a * b_lo
                    }
                }
            }
        }

        if (i + 3 < NCHUNK) load_stage(i + 3, (i + 3) & 3);
    }

    #pragma unroll
    for (int mt = 0; mt < 4; ++mt) {
        #pragma unroll
        for (int nt = 0; nt < 8; ++nt) {
            const float* c = acc[mt][nt];
            int row = m0 + wm * 64 + mt * 16 + (L >> 2);
            int col = wn * 64 + nt * 8 + (L & 3) * 2;
            float2 v0, v1;
            v0.x = fmaxf(c[0], 0.0f); v0.y = fmaxf(c[1], 0.0f);
            v1.x = fmaxf(c[2], 0.0f); v1.y = fmaxf(c[3], 0.0f);
            *(float2*)(out + (size_t)row * OUTC + col)       = v0;
            *(float2*)(out + (size_t)(row + 8) * OUTC + col) = v1;
        }
    }
}

// ---------------------------------------------------------------------------
// Launch
// ---------------------------------------------------------------------------
extern "C" void kernel_launch(void* const* d_in, const int* in_sizes, int n_in,
                              void* d_out, int out_size)
{
    const float* xyz1  = (const float*)d_in[0];
    const float* feat1 = (const float*)d_in[1];
    const float* xyz2  = (const float*)d_in[2];
    const float* feat2 = (const float*)d_in[3];
    const float* kp    = (const float*)d_in[4];
    const float* W     = (const float*)d_in[5];
    float* out = (float*)d_out;

    cudaFuncSetAttribute(gemm_kernel,
                         cudaFuncAttributeMaxDynamicSharedMemorySize, GEMM_SMEM);

    prep_kernel<<<BATCH + (KDIM * FOUT) / 512, 512>>>(xyz1, W);
    knn_kernel<<<dim3(N2 / 256, BATCH), 256>>>(xyz2);
    wf_kernel<<<NQ / 4, 128>>>(xyz1, feat1, xyz2, kp);
    gemm_kernel<<<NQ / 256, 256, GEMM_SMEM>>>(feat2, out);
}

// round 11
// speedup vs baseline: 1.3883x; 1.1467x over previous
#include <cuda_runtime.h>
#include <cuda_fp16.h>
#include <cstdint>

// ---------------------------------------------------------------------------
// Problem constants
// ---------------------------------------------------------------------------
#define BATCH   4
#define N1      2048
#define N2      8192
#define C1      128
#define C2      64
#define KP      15
#define FOUT    128
#define NSAMP   16
#define NQ      (BATCH * N2)          // 32768 queries
#define KDIM    (KP * C1)             // 1920
#define OUTC    (FOUT + C2)           // 192
#define NCHUNK  (KDIM / 32)           // 60 K-chunks of 32 fp16 (64B rows)

#define GRID    8                     // 8x8x8 spatial bins
#define NCELL   (GRID * GRID * GRID)  // 512
#define CELLH   0.125f

// Scratch (device globals)
__device__ int     g_idx[NQ * NSAMP];
__device__ float4  g_sxyz[BATCH * N1];        // binned points (x,y,z,idx)
__device__ int     g_cellstart[BATCH * (NCELL + 1)];
__device__ __half  g_a[(size_t)NQ * KDIM];    // wf in fp16, row-major (q, kc)
__device__ __half  g_b[(size_t)FOUT * KDIM];  // W^T in fp16, (f, kc)

// ---------------------------------------------------------------------------
// Helpers
// ---------------------------------------------------------------------------
__device__ __forceinline__ uint32_t smem_u32(const void* p) {
    uint32_t a;
    asm("{ .reg .u64 t; cvta.to.shared.u64 t, %1; cvt.u32.u64 %0, t; }"
        : "=r"(a) : "l"(p));
    return a;
}
__device__ __forceinline__ void ldsm4(uint32_t* r, uint32_t addr) {
    asm volatile("ldmatrix.sync.aligned.m8n8.x4.shared.b16 {%0,%1,%2,%3}, [%4];"
                 : "=r"(r[0]), "=r"(r[1]), "=r"(r[2]), "=r"(r[3]) : "r"(addr));
}
__device__ __forceinline__ void mma16816h(float* c, const uint32_t* a,
                                          const uint32_t* b) {
    asm volatile(
        "mma.sync.aligned.m16n8k16.row.col.f32.f16.f16.f32 "
        "{%0,%1,%2,%3}, {%4,%5,%6,%7}, {%8,%9}, {%0,%1,%2,%3};"
        : "+f"(c[0]), "+f"(c[1]), "+f"(c[2]), "+f"(c[3])
        : "r"(a[0]), "r"(a[1]), "r"(a[2]), "r"(a[3]), "r"(b[0]), "r"(b[1]));
}
__device__ __forceinline__ int cellof(float x) {
    int c = (int)(x * (float)GRID);
    return min(GRID - 1, max(0, c));
}

// packed f32x2 (sm_100+ PTX, base family feature)
#define FFMA2(acc, a, b) \
    asm("fma.rn.f32x2 %0, %1, %2, %0;" : "+l"(acc) : "l"(a), "l"(b))
#define PACKF2(out, lo, hi) \
    asm("mov.b64 %0, {%1, %2};" : "=l"(out) : "f"(lo), "f"(hi))
#define UNPACKF2(lo, hi, in) \
    asm("mov.b64 {%0, %1}, %2;" : "=f"(lo), "=f"(hi) : "l"(in))

// 64B-row smem swizzle: quad (16B) index XORed with ((row>>1)&3)
__device__ __forceinline__ uint32_t sw64(int row, int kb) {
    return row * 64 + (kb ^ (((row >> 1) & 3) << 4));
}

// ---------------------------------------------------------------------------
// Kernel 0: prep = spatial binning (blocks 0..3) + W fp16 transpose (4..483)
// ---------------------------------------------------------------------------
__global__ __launch_bounds__(512) void prep_kernel(
    const float* __restrict__ xyz1, const float* __restrict__ W)
{
    const int t = threadIdx.x;

    if (blockIdx.x >= BATCH) {
        const int i = (blockIdx.x - BATCH) * 512 + t;
        const int kc = i / FOUT;
        const int f  = i % FOUT;
        g_b[(size_t)f * KDIM + kc] = __float2half_rn(W[i]);
        return;
    }

    __shared__ int cnt[NCELL];
    __shared__ int sscan[NCELL];
    __shared__ int cursor[NCELL];

    const int b = blockIdx.x;
    cnt[t] = 0;
    __syncthreads();

    float px[N1 / 512], py[N1 / 512], pz[N1 / 512];
    int   cl[N1 / 512];
    #pragma unroll
    for (int k = 0; k < N1 / 512; ++k) {
        const int i = t + k * 512;
        px[k] = xyz1[((size_t)b * N1 + i) * 3 + 0];
        py[k] = xyz1[((size_t)b * N1 + i) * 3 + 1];
        pz[k] = xyz1[((size_t)b * N1 + i) * 3 + 2];
        cl[k] = (cellof(pz[k]) << 6) | (cellof(py[k]) << 3) | cellof(px[k]);
        atomicAdd(&cnt[cl[k]], 1);
    }
    __syncthreads();

    sscan[t] = cnt[t];
    __syncthreads();
    #pragma unroll
    for (int off = 1; off < NCELL; off <<= 1) {
        int add = (t >= off) ? sscan[t - off] : 0;
        __syncthreads();
        sscan[t] += add;
        __syncthreads();
    }
    const int excl = sscan[t] - cnt[t];
    g_cellstart[b * (NCELL + 1) + t] = excl;
    if (t == NCELL - 1) g_cellstart[b * (NCELL + 1) + NCELL] = N1;
    cursor[t] = excl;
    __syncthreads();

    #pragma unroll
    for (int k = 0; k < N1 / 512; ++k) {
        const int i = t + k * 512;
        const int pos = atomicAdd(&cursor[cl[k]], 1);
        g_sxyz[b * N1 + pos] = make_float4(px[k], py[k], pz[k], __int_as_float(i));
    }
}

// ---------------------------------------------------------------------------
// Kernel 1: kNN via expanding Chebyshev shells, contiguous row-run scans.
// ---------------------------------------------------------------------------
__global__ __launch_bounds__(256) void knn_kernel(const float* __restrict__ xyz2)
{
    __shared__ float4 spt[N1];            // 32KB
    __shared__ int    cst[NCELL + 1];

    const int b = blockIdx.y;
    for (int i = threadIdx.x; i < N1; i += 256)
        spt[i] = g_sxyz[b * N1 + i];
    for (int i = threadIdx.x; i < NCELL + 1; i += 256)
        cst[i] = g_cellstart[b * (NCELL + 1) + i];
    __syncthreads();

    const int q = b * N2 + blockIdx.x * 256 + threadIdx.x;
    const float qx = xyz2[q * 3 + 0];
    const float qy = xyz2[q * 3 + 1];
    const float qz = xyz2[q * 3 + 2];
    const int cx = cellof(qx), cy = cellof(qy), cz = cellof(qz);

    float dk[NSAMP];
    int   ik[NSAMP];
    #pragma unroll
    for (int p = 0; p < NSAMP; ++p) { dk[p] = 3.4e38f; ik[p] = 0; }

    auto scan_run = [&](int rowbase, int xa, int xb) {
        const int pe = cst[rowbase + xb + 1];
        for (int p = cst[rowbase + xa]; p < pe; ++p) {
            const float4 P = spt[p];
            const float dx = qx - P.x;
            const float dy = qy - P.y;
            const float dz = qz - P.z;
            const float d2 = fmaf(dx, dx, fmaf(dy, dy, dz * dz));
            if (d2 < dk[NSAMP - 1]) {
                dk[NSAMP - 1] = d2;
                ik[NSAMP - 1] = __float_as_int(P.w);
                #pragma unroll
                for (int s = NSAMP - 1; s > 0; --s) {
                    if (dk[s] < dk[s - 1]) {
                        float td = dk[s]; dk[s] = dk[s-1]; dk[s-1] = td;
                        int   ti = ik[s]; ik[s] = ik[s-1]; ik[s-1] = ti;
                    }
                }
            }
        }
    };

    for (int R = 0; R < GRID; ++R) {
        const int zlo = max(cz - R, 0), zhi = min(cz + R, GRID - 1);
        const int ylo = max(cy - R, 0), yhi = min(cy + R, GRID - 1);
        const int xlo = max(cx - R, 0), xhi = min(cx + R, GRID - 1);
        for (int z = zlo; z <= zhi; ++z) {
            const int az = abs(z - cz);
            for (int y = ylo; y <= yhi; ++y) {
                const int ay = abs(y - cy);
                const int rowbase = (z << 6) | (y << 3);
                if (az == R || ay == R) {
                    scan_run(rowbase, xlo, xhi);       // full row in shell
                } else {
                    if (cx - R >= 0)        scan_run(rowbase, cx - R, cx - R);
                    if (cx + R <= GRID - 1) scan_run(rowbase, cx + R, cx + R);
                }
            }
        }
        const float bnd = (float)R * CELLH;
        if (dk[NSAMP - 1] < bnd * bnd) break;
    }

    int* o = g_idx + q * NSAMP;
    #pragma unroll
    for (int p = 0; p < NSAMP; ++p) o[p] = ik[p];
}

// ---------------------------------------------------------------------------
// Kernel 2: weighted aggregation, fp16 output (single array).
// ---------------------------------------------------------------------------
__global__ __launch_bounds__(128) void wf_kernel(
    const float* __restrict__ xyz1, const float* __restrict__ feat1,
    const float* __restrict__ xyz2, const float* __restrict__ kp)
{
    const int wid = threadIdx.x >> 5;
    const int L   = threadIdx.x & 31;
    const int q   = blockIdx.x * 4 + wid;
    const int b   = q >> 13;

    __shared__ float  skp[KP * 3];
    __shared__ float2 sw2[4][NSAMP][KP];

    if (threadIdx.x < KP * 3) skp[threadIdx.x] = kp[threadIdx.x];
    __syncthreads();

    int sid = 0;
    if (L < NSAMP) {
        sid = g_idx[q * NSAMP + L];
        const float rx = xyz1[((size_t)b * N1 + sid) * 3 + 0] - xyz2[q * 3 + 0];
        const float ry = xyz1[((size_t)b * N1 + sid) * 3 + 1] - xyz2[q * 3 + 1];
        const float rz = xyz1[((size_t)b * N1 + sid) * 3 + 2] - xyz2[q * 3 + 2];
        #pragma unroll
        for (int k = 0; k < KP; ++k) {
            float dx = rx - skp[k * 3 + 0];
            float dy = ry - skp[k * 3 + 1];
            float dz = rz - skp[k * 3 + 2];
            float sq = dx * dx + dy * dy + dz * dz;
            float dist = sqrtf(fmaxf(sq, 1e-12f));
            float wt = fmaxf(0.0f, 1.0f - dist / 0.2f);
            sw2[wid][L][k] = make_float2(wt, wt);
        }
    }
    __syncwarp();

    const float* fb = feat1 + (size_t)b * N1 * C1;
    unsigned long long fxy[NSAMP], fzw[NSAMP];
    #pragma unroll
    for (int s = 0; s < NSAMP; ++s) {
        const int is = __shfl_sync(0xffffffffu, sid, s);
        const float4 v = *(const float4*)(fb + (size_t)is * C1 + 4 * L);
        PACKF2(fxy[s], v.x, v.y);
        PACKF2(fzw[s], v.z, v.w);
    }

    unsigned long long a0[KP], a1[KP];
    #pragma unroll
    for (int k = 0; k < KP; ++k) { a0[k] = 0ull; a1[k] = 0ull; }

    #pragma unroll
    for (int s = 0; s < NSAMP; ++s) {
        #pragma unroll
        for (int k = 0; k < KP; ++k) {
            const unsigned long long wp =
                *(const unsigned long long*)&sw2[wid][s][k];
            FFMA2(a0[k], wp, fxy[s]);
            FFMA2(a1[k], wp, fzw[s]);
        }
    }

    const size_t qbase = (size_t)q * KDIM + 4 * L;
    #pragma unroll
    for (int k = 0; k < KP; ++k) {
        float vx, vy, vz, vw;
        UNPACKF2(vx, vy, a0[k]);
        UNPACKF2(vz, vw, a1[k]);
        __half2 h0 = __floats2half2_rn(vx, vy);
        __half2 h1 = __floats2half2_rn(vz, vw);
        uint2 st;
        st.x = *(const uint32_t*)&h0;
        st.y = *(const uint32_t*)&h1;
        *(uint2*)(g_a + qbase + k * C1) = st;
    }
}

// ---------------------------------------------------------------------------
// Kernel 3: mma.sync pure fp16 GEMM (1 product), fused concat.
// M=32768 (128 CTAs of 256 rows), N=128, K=1920 in 60 chunks of 32 (64B rows).
// 8 warps in 4(M)x2(N): warp tile 64x64. 4-stage cp.async (24KB/stage).
// ---------------------------------------------------------------------------
#define A_SUB       16384               // 256 rows x 64B
#define B_SUB       8192                // 128 rows x 64B
#define STAGE_BYTES (A_SUB + B_SUB)           // 24KB
#define NSTAGE      4
#define GEMM_SMEM   (NSTAGE * STAGE_BYTES)    // 96KB

__global__ __launch_bounds__(256, 1)
void gemm_kernel(const float* __restrict__ feat2, float* __restrict__ out)
{
    extern __shared__ __align__(1024) char dsmem[];

    const int tid = threadIdx.x;
    const int wid = tid >> 5;
    const int L   = tid & 31;
    const int m0  = blockIdx.x * 256;
    const int wm  = wid & 3;              // 0..3 (M, 64 rows each)
    const int wn  = wid >> 2;             // 0..1 (N, 64 cols each)

    const uint32_t base = smem_u32(dsmem);

    const char* srcA = (const char*)g_a + (size_t)m0 * (KDIM * 2);
    const char* srcB = (const char*)g_b;

    // one stage: A 256 rows x 4 quads (1024), B 128 rows x 4 quads (512)
    auto load_stage = [&](int chunk, int buf) {
        const uint32_t sbase = base + buf * STAGE_BYTES;
        #pragma unroll
        for (int v = 0; v < 4; ++v) {
            int idx = v * 256 + tid;          // 0..1023
            int row = idx >> 2;               // 0..255
            int kb  = (idx & 3) << 4;         // 0..48
            const char* g = srcA + (size_t)row * (KDIM * 2) + chunk * 64 + kb;
            uint32_t sa = sbase + sw64(row, kb);
            asm volatile("cp.async.cg.shared.global [%0], [%1], 16;"
                         :: "r"(sa), "l"(g));
        }
        #pragma unroll
        for (int v = 0; v < 2; ++v) {
            int idx = v * 256 + tid;          // 0..511
            int row = idx >> 2;               // 0..127
            int kb  = (idx & 3) << 4;
            const char* g = srcB + (size_t)row * (KDIM * 2) + chunk * 64 + kb;
            uint32_t sa = sbase + A_SUB + sw64(row, kb);
            asm volatile("cp.async.cg.shared.global [%0], [%1], 16;"
                         :: "r"(sa), "l"(g));
        }
        asm volatile("cp.async.commit_group;" ::: "memory");
    };

    // ldmatrix per-thread offsets (64B rows, quad swizzle)
    int aRow = wm * 64 + (L & 15);                  // + mt*16
    int aKb  = (L >> 4) * 16;                       // 0 or 16
    int bRow = wn * 64 + ((L >> 4) << 3) + (L & 7); // + ng*16
    int bKb  = ((L >> 3) & 1) * 16;

    uint32_t aOff[4], aXor[4];
    #pragma unroll
    for (int mt = 0; mt < 4; ++mt) {
        int r = aRow + mt * 16;
        aOff[mt] = r * 64;
        aXor[mt] = ((r >> 1) & 3) << 4;
    }
    uint32_t bOff[4], bXor[4];
    #pragma unroll
    for (int ng = 0; ng < 4; ++ng) {
        int r = bRow + ng * 16;
        bOff[ng] = r * 64;
        bXor[ng] = ((r >> 1) & 3) << 4;
    }

    float acc[4][8][4];
    #pragma unroll
    for (int i = 0; i < 4; ++i)
        #pragma unroll
        for (int j = 0; j < 8; ++j)
            #pragma unroll
            for (int k = 0; k < 4; ++k) acc[i][j][k] = 0.0f;

    load_stage(0, 0);
    load_stage(1, 1);
    load_stage(2, 2);

    // fused concat: copy feat2 rows [m0, m0+256) into out[:,128:192)
    {
        const float* f2 = feat2 + (size_t)m0 * C2;
        float* o2 = out + (size_t)m0 * OUTC + FOUT;
        #pragma unroll
        for (int i = 0; i < 16; ++i) {
            int v = i * 256 + tid;            // 0..4095
            int row = v >> 4;
            int j   = v & 15;
            float4 t = *(const float4*)(f2 + (size_t)row * C2 + j * 4);
            *(float4*)(o2 + (size_t)row * OUTC + j * 4) = t;
        }
    }

    for (int i = 0; i < NCHUNK; ++i) {
        const int buf = i & 3;
        if (i + 2 < NCHUNK)
            asm volatile("cp.async.wait_group 2;" ::: "memory");
        else if (i + 1 < NCHUNK)
            asm volatile("cp.async.wait_group 1;" ::: "memory");
        else
            asm volatile("cp.async.wait_group 0;" ::: "memory");
        __syncthreads();

        const uint32_t sb = base + buf * STAGE_BYTES;
        const uint32_t sA = sb;
        const uint32_t sB = sb + A_SUB;

        #pragma unroll
        for (int ks = 0; ks < 2; ++ks) {
            const uint32_t kA = ks * 32 + aKb;
            const uint32_t kB = ks * 32 + bKb;
            uint32_t a[4][4];
            #pragma unroll
            for (int mt = 0; mt < 4; ++mt)
                ldsm4(a[mt], sA + aOff[mt] + (kA ^ aXor[mt]));
            #pragma unroll
            for (int ng = 0; ng < 4; ++ng) {
                uint32_t bb[4];
                ldsm4(bb, sB + bOff[ng] + (kB ^ bXor[ng]));
                #pragma unroll
                for (int mt = 0; mt < 4; ++mt) {
                    mma16816h(acc[mt][ng * 2 + 0], a[mt], &bb[0]);
                    mma16816h(acc[mt][ng * 2 + 1], a[mt], &bb[2]);
                }
            }
        }

        if (i + 3 < NCHUNK) load_stage(i + 3, (i + 3) & 3);
    }

    #pragma unroll
    for (int mt = 0; mt < 4; ++mt) {
        #pragma unroll
        for (int nt = 0; nt < 8; ++nt) {
            const float* c = acc[mt][nt];
            int row = m0 + wm * 64 + mt * 16 + (L >> 2);
            int col = wn * 64 + nt * 8 + (L & 3) * 2;
            float2 v0, v1;
            v0.x = fmaxf(c[0], 0.0f); v0.y = fmaxf(c[1], 0.0f);
            v1.x = fmaxf(c[2], 0.0f); v1.y = fmaxf(c[3], 0.0f);
            *(float2*)(out + (size_t)row * OUTC + col)       = v0;
            *(float2*)(out + (size_t)(row + 8) * OUTC + col) = v1;
        }
    }
}

// ---------------------------------------------------------------------------
// Launch
// ---------------------------------------------------------------------------
extern "C" void kernel_launch(void* const* d_in, const int* in_sizes, int n_in,
                              void* d_out, int out_size)
{
    const float* xyz1  = (const float*)d_in[0];
    const float* feat1 = (const float*)d_in[1];
    const float* xyz2  = (const float*)d_in[2];
    const float* feat2 = (const float*)d_in[3];
    const float* kp    = (const float*)d_in[4];
    const float* W     = (const float*)d_in[5];
    float* out = (float*)d_out;

    cudaFuncSetAttribute(gemm_kernel,
                         cudaFuncAttributeMaxDynamicSharedMemorySize, GEMM_SMEM);

    prep_kernel<<<BATCH + (KDIM * FOUT) / 512, 512>>>(xyz1, W);
    knn_kernel<<<dim3(N2 / 256, BATCH), 256>>>(xyz2);
    wf_kernel<<<NQ / 4, 128>>>(xyz1, feat1, xyz2, kp);
    gemm_kernel<<<NQ / 256, 256, GEMM_SMEM>>>(feat2, out);
}

// round 12
// speedup vs baseline: 1.3908x; 1.0018x over previous
#include <cuda_runtime.h>
#include <cuda_fp16.h>
#include <cstdint>

// ---------------------------------------------------------------------------
// Problem constants
// ---------------------------------------------------------------------------
#define BATCH   4
#define N1      2048
#define N2      8192
#define C1      128
#define C2      64
#define KP      15
#define FOUT    128
#define NSAMP   16
#define NQ      (BATCH * N2)          // 32768 queries
#define KDIM    (KP * C1)             // 1920
#define OUTC    (FOUT + C2)           // 192
#define NCHUNK  (KDIM / 32)           // 60 K-chunks of 32 fp16 (64B rows)

#define GRID    8                     // 8x8x8 spatial bins
#define NCELL   (GRID * GRID * GRID)  // 512
#define CELLH   0.125f

// Scratch (device globals)
__device__ int     g_idx[NQ * NSAMP];
__device__ float4  g_sxyz[BATCH * N1];        // binned points (x,y,z,idx)
__device__ int     g_cellstart[BATCH * (NCELL + 1)];
__device__ __half  g_a[(size_t)NQ * KDIM];    // wf in fp16, row-major (q, kc)
__device__ __half  g_b[(size_t)FOUT * KDIM];  // W^T in fp16, (f, kc)

// ---------------------------------------------------------------------------
// Helpers
// ---------------------------------------------------------------------------
__device__ __forceinline__ uint32_t smem_u32(const void* p) {
    uint32_t a;
    asm("{ .reg .u64 t; cvta.to.shared.u64 t, %1; cvt.u32.u64 %0, t; }"
        : "=r"(a) : "l"(p));
    return a;
}
__device__ __forceinline__ void ldsm4(uint32_t* r, uint32_t addr) {
    asm volatile("ldmatrix.sync.aligned.m8n8.x4.shared.b16 {%0,%1,%2,%3}, [%4];"
                 : "=r"(r[0]), "=r"(r[1]), "=r"(r[2]), "=r"(r[3]) : "r"(addr));
}
__device__ __forceinline__ void mma16816h(float* c, const uint32_t* a,
                                          const uint32_t* b) {
    asm volatile(
        "mma.sync.aligned.m16n8k16.row.col.f32.f16.f16.f32 "
        "{%0,%1,%2,%3}, {%4,%5,%6,%7}, {%8,%9}, {%0,%1,%2,%3};"
        : "+f"(c[0]), "+f"(c[1]), "+f"(c[2]), "+f"(c[3])
        : "r"(a[0]), "r"(a[1]), "r"(a[2]), "r"(a[3]), "r"(b[0]), "r"(b[1]));
}
__device__ __forceinline__ int cellof(float x) {
    int c = (int)(x * (float)GRID);
    return min(GRID - 1, max(0, c));
}

// packed f32x2 (sm_100+ PTX, base family feature)
#define FFMA2(acc, a, b) \
    asm("fma.rn.f32x2 %0, %1, %2, %0;" : "+l"(acc) : "l"(a), "l"(b))
#define PACKF2(out, lo, hi) \
    asm("mov.b64 %0, {%1, %2};" : "=l"(out) : "f"(lo), "f"(hi))
#define UNPACKF2(lo, hi, in) \
    asm("mov.b64 {%0, %1}, %2;" : "=f"(lo), "=f"(hi) : "l"(in))

// 64B-row smem swizzle: quad (16B) index XORed with ((row>>1)&3)
__device__ __forceinline__ uint32_t sw64(int row, int kb) {
    return row * 64 + (kb ^ (((row >> 1) & 3) << 4));
}

// ---------------------------------------------------------------------------
// Kernel 0: prep = spatial binning (blocks 0..3) + W fp16 transpose (4..483)
// ---------------------------------------------------------------------------
__global__ __launch_bounds__(512) void prep_kernel(
    const float* __restrict__ xyz1, const float* __restrict__ W)
{
    const int t = threadIdx.x;

    if (blockIdx.x >= BATCH) {
        const int i = (blockIdx.x - BATCH) * 512 + t;
        const int kc = i / FOUT;
        const int f  = i % FOUT;
        g_b[(size_t)f * KDIM + kc] = __float2half_rn(W[i]);
        return;
    }

    __shared__ int cnt[NCELL];
    __shared__ int sscan[NCELL];
    __shared__ int cursor[NCELL];

    const int b = blockIdx.x;
    cnt[t] = 0;
    __syncthreads();

    float px[N1 / 512], py[N1 / 512], pz[N1 / 512];
    int   cl[N1 / 512];
    #pragma unroll
    for (int k = 0; k < N1 / 512; ++k) {
        const int i = t + k * 512;
        px[k] = xyz1[((size_t)b * N1 + i) * 3 + 0];
        py[k] = xyz1[((size_t)b * N1 + i) * 3 + 1];
        pz[k] = xyz1[((size_t)b * N1 + i) * 3 + 2];
        cl[k] = (cellof(pz[k]) << 6) | (cellof(py[k]) << 3) | cellof(px[k]);
        atomicAdd(&cnt[cl[k]], 1);
    }
    __syncthreads();

    sscan[t] = cnt[t];
    __syncthreads();
    #pragma unroll
    for (int off = 1; off < NCELL; off <<= 1) {
        int add = (t >= off) ? sscan[t - off] : 0;
        __syncthreads();
        sscan[t] += add;
        __syncthreads();
    }
    const int excl = sscan[t] - cnt[t];
    g_cellstart[b * (NCELL + 1) + t] = excl;
    if (t == NCELL - 1) g_cellstart[b * (NCELL + 1) + NCELL] = N1;
    cursor[t] = excl;
    __syncthreads();

    #pragma unroll
    for (int k = 0; k < N1 / 512; ++k) {
        const int i = t + k * 512;
        const int pos = atomicAdd(&cursor[cl[k]], 1);
        g_sxyz[b * N1 + pos] = make_float4(px[k], py[k], pz[k], __int_as_float(i));
    }
}

// ---------------------------------------------------------------------------
// Kernel 1: kNN via expanding Chebyshev shells, contiguous row-run scans.
// ---------------------------------------------------------------------------
__global__ __launch_bounds__(256) void knn_kernel(const float* __restrict__ xyz2)
{
    __shared__ float4 spt[N1];            // 32KB
    __shared__ int    cst[NCELL + 1];

    const int b = blockIdx.y;
    for (int i = threadIdx.x; i < N1; i += 256)
        spt[i] = g_sxyz[b * N1 + i];
    for (int i = threadIdx.x; i < NCELL + 1; i += 256)
        cst[i] = g_cellstart[b * (NCELL + 1) + i];
    __syncthreads();

    const int q = b * N2 + blockIdx.x * 256 + threadIdx.x;
    const float qx = xyz2[q * 3 + 0];
    const float qy = xyz2[q * 3 + 1];
    const float qz = xyz2[q * 3 + 2];
    const int cx = cellof(qx), cy = cellof(qy), cz = cellof(qz);

    float dk[NSAMP];
    int   ik[NSAMP];
    #pragma unroll
    for (int p = 0; p < NSAMP; ++p) { dk[p] = 3.4e38f; ik[p] = 0; }

    auto scan_run = [&](int rowbase, int xa, int xb) {
        const int pe = cst[rowbase + xb + 1];
        for (int p = cst[rowbase + xa]; p < pe; ++p) {
            const float4 P = spt[p];
            const float dx = qx - P.x;
            const float dy = qy - P.y;
            const float dz = qz - P.z;
            const float d2 = fmaf(dx, dx, fmaf(dy, dy, dz * dz));
            if (d2 < dk[NSAMP - 1]) {
                dk[NSAMP - 1] = d2;
                ik[NSAMP - 1] = __float_as_int(P.w);
                #pragma unroll
                for (int s = NSAMP - 1; s > 0; --s) {
                    if (dk[s] < dk[s - 1]) {
                        float td = dk[s]; dk[s] = dk[s-1]; dk[s-1] = td;
                        int   ti = ik[s]; ik[s] = ik[s-1]; ik[s-1] = ti;
                    }
                }
            }
        }
    };

    for (int R = 0; R < GRID; ++R) {
        const int zlo = max(cz - R, 0), zhi = min(cz + R, GRID - 1);
        const int ylo = max(cy - R, 0), yhi = min(cy + R, GRID - 1);
        const int xlo = max(cx - R, 0), xhi = min(cx + R, GRID - 1);
        for (int z = zlo; z <= zhi; ++z) {
            const int az = abs(z - cz);
            for (int y = ylo; y <= yhi; ++y) {
                const int ay = abs(y - cy);
                const int rowbase = (z << 6) | (y << 3);
                if (az == R || ay == R) {
                    scan_run(rowbase, xlo, xhi);       // full row in shell
                } else {
                    if (cx - R >= 0)        scan_run(rowbase, cx - R, cx - R);
                    if (cx + R <= GRID - 1) scan_run(rowbase, cx + R, cx + R);
                }
            }
        }
        const float bnd = (float)R * CELLH;
        if (dk[NSAMP - 1] < bnd * bnd) break;
    }

    int* o = g_idx + q * NSAMP;
    #pragma unroll
    for (int p = 0; p < NSAMP; ++p) o[p] = ik[p];
}

// ---------------------------------------------------------------------------
// Kernel 2: weighted aggregation, fp16 output (single array).
// ---------------------------------------------------------------------------
__global__ __launch_bounds__(128) void wf_kernel(
    const float* __restrict__ xyz1, const float* __restrict__ feat1,
    const float* __restrict__ xyz2, const float* __restrict__ kp)
{
    const int wid = threadIdx.x >> 5;
    const int L   = threadIdx.x & 31;
    const int q   = blockIdx.x * 4 + wid;
    const int b   = q >> 13;

    __shared__ float  skp[KP * 3];
    __shared__ float2 sw2[4][NSAMP][KP];

    if (threadIdx.x < KP * 3) skp[threadIdx.x] = kp[threadIdx.x];
    __syncthreads();

    int sid = 0;
    if (L < NSAMP) {
        sid = g_idx[q * NSAMP + L];
        const float rx = xyz1[((size_t)b * N1 + sid) * 3 + 0] - xyz2[q * 3 + 0];
        const float ry = xyz1[((size_t)b * N1 + sid) * 3 + 1] - xyz2[q * 3 + 1];
        const float rz = xyz1[((size_t)b * N1 + sid) * 3 + 2] - xyz2[q * 3 + 2];
        #pragma unroll
        for (int k = 0; k < KP; ++k) {
            float dx = rx - skp[k * 3 + 0];
            float dy = ry - skp[k * 3 + 1];
            float dz = rz - skp[k * 3 + 2];
            float sq = dx * dx + dy * dy + dz * dz;
            float dist = sqrtf(fmaxf(sq, 1e-12f));
            float wt = fmaxf(0.0f, 1.0f - dist / 0.2f);
            sw2[wid][L][k] = make_float2(wt, wt);
        }
    }
    __syncwarp();

    const float* fb = feat1 + (size_t)b * N1 * C1;
    unsigned long long fxy[NSAMP], fzw[NSAMP];
    #pragma unroll
    for (int s = 0; s < NSAMP; ++s) {
        const int is = __shfl_sync(0xffffffffu, sid, s);
        const float4 v = *(const float4*)(fb + (size_t)is * C1 + 4 * L);
        PACKF2(fxy[s], v.x, v.y);
        PACKF2(fzw[s], v.z, v.w);
    }

    unsigned long long a0[KP], a1[KP];
    #pragma unroll
    for (int k = 0; k < KP; ++k) { a0[k] = 0ull; a1[k] = 0ull; }

    #pragma unroll
    for (int s = 0; s < NSAMP; ++s) {
        #pragma unroll
        for (int k = 0; k < KP; ++k) {
            const unsigned long long wp =
                *(const unsigned long long*)&sw2[wid][s][k];
            FFMA2(a0[k], wp, fxy[s]);
            FFMA2(a1[k], wp, fzw[s]);
        }
    }

    const size_t qbase = (size_t)q * KDIM + 4 * L;
    #pragma unroll
    for (int k = 0; k < KP; ++k) {
        float vx, vy, vz, vw;
        UNPACKF2(vx, vy, a0[k]);
        UNPACKF2(vz, vw, a1[k]);
        __half2 h0 = __floats2half2_rn(vx, vy);
        __half2 h1 = __floats2half2_rn(vz, vw);
        uint2 st;
        st.x = *(const uint32_t*)&h0;
        st.y = *(const uint32_t*)&h1;
        *(uint2*)(g_a + qbase + k * C1) = st;
    }
}

// ---------------------------------------------------------------------------
// Kernel 3: mma.sync pure fp16 GEMM (1 product), fused concat.
// M=32768 (128 CTAs of 256 rows), N=128, K=1920 in 60 chunks of 32 (64B rows).
// 8 warps in 4(M)x2(N): warp tile 64x64. 4-stage cp.async (24KB/stage).
// ---------------------------------------------------------------------------
#define A_SUB       16384               // 256 rows x 64B
#define B_SUB       8192                // 128 rows x 64B
#define STAGE_BYTES (A_SUB + B_SUB)           // 24KB
#define NSTAGE      4
#define GEMM_SMEM   (NSTAGE * STAGE_BYTES)    // 96KB

__global__ __launch_bounds__(256, 1)
void gemm_kernel(const float* __restrict__ feat2, float* __restrict__ out)
{
    extern __shared__ __align__(1024) char dsmem[];

    const int tid = threadIdx.x;
    const int wid = tid >> 5;
    const int L   = tid & 31;
    const int m0  = blockIdx.x * 256;
    const int wm  = wid & 3;              // 0..3 (M, 64 rows each)
    const int wn  = wid >> 2;             // 0..1 (N, 64 cols each)

    const uint32_t base = smem_u32(dsmem);

    const char* srcA = (const char*)g_a + (size_t)m0 * (KDIM * 2);
    const char* srcB = (const char*)g_b;

    // one stage: A 256 rows x 4 quads (1024), B 128 rows x 4 quads (512)
    auto load_stage = [&](int chunk, int buf) {
        const uint32_t sbase = base + buf * STAGE_BYTES;
        #pragma unroll
        for (int v = 0; v < 4; ++v) {
            int idx = v * 256 + tid;          // 0..1023
            int row = idx >> 2;               // 0..255
            int kb  = (idx & 3) << 4;         // 0..48
            const char* g = srcA + (size_t)row * (KDIM * 2) + chunk * 64 + kb;
            uint32_t sa = sbase + sw64(row, kb);
            asm volatile("cp.async.cg.shared.global [%0], [%1], 16;"
                         :: "r"(sa), "l"(g));
        }
        #pragma unroll
        for (int v = 0; v < 2; ++v) {
            int idx = v * 256 + tid;          // 0..511
            int row = idx >> 2;               // 0..127
            int kb  = (idx & 3) << 4;
            const char* g = srcB + (size_t)row * (KDIM * 2) + chunk * 64 + kb;
            uint32_t sa = sbase + A_SUB + sw64(row, kb);
            asm volatile("cp.async.cg.shared.global [%0], [%1], 16;"
                         :: "r"(sa), "l"(g));
        }
        asm volatile("cp.async.commit_group;" ::: "memory");
    };

    // ldmatrix per-thread offsets (64B rows, quad swizzle)
    int aRow = wm * 64 + (L & 15);                  // + mt*16
    int aKb  = (L >> 4) * 16;                       // 0 or 16
    int bRow = wn * 64 + ((L >> 4) << 3) + (L & 7); // + ng*16
    int bKb  = ((L >> 3) & 1) * 16;

    uint32_t aOff[4], aXor[4];
    #pragma unroll
    for (int mt = 0; mt < 4; ++mt) {
        int r = aRow + mt * 16;
        aOff[mt] = r * 64;
        aXor[mt] = ((r >> 1) & 3) << 4;
    }
    uint32_t bOff[4], bXor[4];
    #pragma unroll
    for (int ng = 0; ng < 4; ++ng) {
        int r = bRow + ng * 16;
        bOff[ng] = r * 64;
        bXor[ng] = ((r >> 1) & 3) << 4;
    }

    float acc[4][8][4];
    #pragma unroll
    for (int i = 0; i < 4; ++i)
        #pragma unroll
        for (int j = 0; j < 8; ++j)
            #pragma unroll
            for (int k = 0; k < 4; ++k) acc[i][j][k] = 0.0f;

    load_stage(0, 0);
    load_stage(1, 1);
    load_stage(2, 2);

    // fused concat: copy feat2 rows [m0, m0+256) into out[:,128:192)
    {
        const float* f2 = feat2 + (size_t)m0 * C2;
        float* o2 = out + (size_t)m0 * OUTC + FOUT;
        #pragma unroll
        for (int i = 0; i < 16; ++i) {
            int v = i * 256 + tid;            // 0..4095
            int row = v >> 4;
            int j   = v & 15;
            float4 t = *(const float4*)(f2 + (size_t)row * C2 + j * 4);
            *(float4*)(o2 + (size_t)row * OUTC + j * 4) = t;
        }
    }

    for (int i = 0; i < NCHUNK; ++i) {
        const int buf = i & 3;
        if (i + 2 < NCHUNK)
            asm volatile("cp.async.wait_group 2;" ::: "memory");
        else if (i + 1 < NCHUNK)
            asm volatile("cp.async.wait_group 1;" ::: "memory");
        else
            asm volatile("cp.async.wait_group 0;" ::: "memory");
        __syncthreads();

        const uint32_t sb = base + buf * STAGE_BYTES;
        const uint32_t sA = sb;
        const uint32_t sB = sb + A_SUB;

        #pragma unroll
        for (int ks = 0; ks < 2; ++ks) {
            const uint32_t kA = ks * 32 + aKb;
            const uint32_t kB = ks * 32 + bKb;
            uint32_t a[4][4];
            #pragma unroll
            for (int mt = 0; mt < 4; ++mt)
                ldsm4(a[mt], sA + aOff[mt] + (kA ^ aXor[mt]));
            #pragma unroll
            for (int ng = 0; ng < 4; ++ng) {
                uint32_t bb[4];
                ldsm4(bb, sB + bOff[ng] + (kB ^ bXor[ng]));
                #pragma unroll
                for (int mt = 0; mt < 4; ++mt) {
                    mma16816h(acc[mt][ng * 2 + 0], a[mt], &bb[0]);
                    mma16816h(acc[mt][ng * 2 + 1], a[mt], &bb[2]);
                }
            }
        }

        if (i + 3 < NCHUNK) load_stage(i + 3, (i + 3) & 3);
    }

    #pragma unroll
    for (int mt = 0; mt < 4; ++mt) {
        #pragma unroll
        for (int nt = 0; nt < 8; ++nt) {
            const float* c = acc[mt][nt];
            int row = m0 + wm * 64 + mt * 16 + (L >> 2);
            int col = wn * 64 + nt * 8 + (L & 3) * 2;
            float2 v0, v1;
            v0.x = fmaxf(c[0], 0.0f); v0.y = fmaxf(c[1], 0.0f);
            v1.x = fmaxf(c[2], 0.0f); v1.y = fmaxf(c[3], 0.0f);
            *(float2*)(out + (size_t)row * OUTC + col)       = v0;
            *(float2*)(out + (size_t)(row + 8) * OUTC + col) = v1;
        }
    }
}

// ---------------------------------------------------------------------------
// Launch
// ---------------------------------------------------------------------------
extern "C" void kernel_launch(void* const* d_in, const int* in_sizes, int n_in,
                              void* d_out, int out_size)
{
    const float* xyz1  = (const float*)d_in[0];
    const float* feat1 = (const float*)d_in[1];
    const float* xyz2  = (const float*)d_in[2];
    const float* feat2 = (const float*)d_in[3];
    const float* kp    = (const float*)d_in[4];
    const float* W     = (const float*)d_in[5];
    float* out = (float*)d_out;

    cudaFuncSetAttribute(gemm_kernel,
                         cudaFuncAttributeMaxDynamicSharedMemorySize, GEMM_SMEM);

    prep_kernel<<<BATCH + (KDIM * FOUT) / 512, 512>>>(xyz1, W);
    knn_kernel<<<dim3(N2 / 256, BATCH), 256>>>(xyz2);
    wf_kernel<<<NQ / 4, 128>>>(xyz1, feat1, xyz2, kp);
    gemm_kernel<<<NQ / 256, 256, GEMM_SMEM>>>(feat2, out);
}

// round 13
// speedup vs baseline: 1.3910x; 1.0001x over previous
#include <cuda_runtime.h>
#include <cuda_fp16.h>
#include <cstdint>

// ---------------------------------------------------------------------------
// Problem constants
// ---------------------------------------------------------------------------
#define BATCH   4
#define N1      2048
#define N2      8192
#define C1      128
#define C2      64
#define KP      15
#define FOUT    128
#define NSAMP   16
#define NQ      (BATCH * N2)          // 32768 queries
#define KDIM    (KP * C1)             // 1920
#define OUTC    (FOUT + C2)           // 192
#define NCHUNK  (KDIM / 32)           // 60 K-chunks of 32 fp16 (64B rows)

#define GRID    8                     // 8x8x8 spatial bins
#define NCELL   (GRID * GRID * GRID)  // 512
#define CELLH   0.125f

// Scratch (device globals)
__device__ int     g_idx[NQ * NSAMP];
__device__ float4  g_sxyz[BATCH * N1];        // binned points (x,y,z,idx)
__device__ int     g_cellstart[BATCH * (NCELL + 1)];
__device__ __half  g_a[(size_t)NQ * KDIM];    // wf in fp16, row-major (q, kc)
__device__ __half  g_b[(size_t)FOUT * KDIM];  // W^T in fp16, (f, kc)

// ---------------------------------------------------------------------------
// Helpers
// ---------------------------------------------------------------------------
__device__ __forceinline__ uint32_t smem_u32(const void* p) {
    uint32_t a;
    asm("{ .reg .u64 t; cvta.to.shared.u64 t, %1; cvt.u32.u64 %0, t; }"
        : "=r"(a) : "l"(p));
    return a;
}
__device__ __forceinline__ void ldsm4(uint32_t* r, uint32_t addr) {
    asm volatile("ldmatrix.sync.aligned.m8n8.x4.shared.b16 {%0,%1,%2,%3}, [%4];"
                 : "=r"(r[0]), "=r"(r[1]), "=r"(r[2]), "=r"(r[3]) : "r"(addr));
}
__device__ __forceinline__ void mma16816h(float* c, const uint32_t* a,
                                          const uint32_t* b) {
    asm volatile(
        "mma.sync.aligned.m16n8k16.row.col.f32.f16.f16.f32 "
        "{%0,%1,%2,%3}, {%4,%5,%6,%7}, {%8,%9}, {%0,%1,%2,%3};"
        : "+f"(c[0]), "+f"(c[1]), "+f"(c[2]), "+f"(c[3])
        : "r"(a[0]), "r"(a[1]), "r"(a[2]), "r"(a[3]), "r"(b[0]), "r"(b[1]));
}
__device__ __forceinline__ int cellof(float x) {
    int c = (int)(x * (float)GRID);
    return min(GRID - 1, max(0, c));
}

// packed f32x2 (sm_100+ PTX, base family feature)
#define FFMA2(acc, a, b) \
    asm("fma.rn.f32x2 %0, %1, %2, %0;" : "+l"(acc) : "l"(a), "l"(b))
#define PACKF2(out, lo, hi) \
    asm("mov.b64 %0, {%1, %2};" : "=l"(out) : "f"(lo), "f"(hi))
#define UNPACKF2(lo, hi, in) \
    asm("mov.b64 {%0, %1}, %2;" : "=f"(lo), "=f"(hi) : "l"(in))

// 64B-row smem swizzle: quad (16B) index XORed with ((row>>1)&3)
__device__ __forceinline__ uint32_t sw64(int row, int kb) {
    return row * 64 + (kb ^ (((row >> 1) & 3) << 4));
}

// ---------------------------------------------------------------------------
// Kernel 0: prep = spatial binning (blocks 0..3) + W fp16 transpose (4..483)
// ---------------------------------------------------------------------------
__global__ __launch_bounds__(512) void prep_kernel(
    const float* __restrict__ xyz1, const float* __restrict__ W)
{
    const int t = threadIdx.x;

    if (blockIdx.x >= BATCH) {
        const int i = (blockIdx.x - BATCH) * 512 + t;
        const int kc = i / FOUT;
        const int f  = i % FOUT;
        g_b[(size_t)f * KDIM + kc] = __float2half_rn(W[i]);
        return;
    }

    __shared__ int cnt[NCELL];
    __shared__ int sscan[NCELL];
    __shared__ int cursor[NCELL];

    const int b = blockIdx.x;
    cnt[t] = 0;
    __syncthreads();

    float px[N1 / 512], py[N1 / 512], pz[N1 / 512];
    int   cl[N1 / 512];
    #pragma unroll
    for (int k = 0; k < N1 / 512; ++k) {
        const int i = t + k * 512;
        px[k] = xyz1[((size_t)b * N1 + i) * 3 + 0];
        py[k] = xyz1[((size_t)b * N1 + i) * 3 + 1];
        pz[k] = xyz1[((size_t)b * N1 + i) * 3 + 2];
        cl[k] = (cellof(pz[k]) << 6) | (cellof(py[k]) << 3) | cellof(px[k]);
        atomicAdd(&cnt[cl[k]], 1);
    }
    __syncthreads();

    sscan[t] = cnt[t];
    __syncthreads();
    #pragma unroll
    for (int off = 1; off < NCELL; off <<= 1) {
        int add = (t >= off) ? sscan[t - off] : 0;
        __syncthreads();
        sscan[t] += add;
        __syncthreads();
    }
    const int excl = sscan[t] - cnt[t];
    g_cellstart[b * (NCELL + 1) + t] = excl;
    if (t == NCELL - 1) g_cellstart[b * (NCELL + 1) + NCELL] = N1;
    cursor[t] = excl;
    __syncthreads();

    #pragma unroll
    for (int k = 0; k < N1 / 512; ++k) {
        const int i = t + k * 512;
        const int pos = atomicAdd(&cursor[cl[k]], 1);
        g_sxyz[b * N1 + pos] = make_float4(px[k], py[k], pz[k], __int_as_float(i));
    }
}

// ---------------------------------------------------------------------------
// Kernel 1: kNN via expanding Chebyshev shells, contiguous row-run scans.
// ---------------------------------------------------------------------------
__global__ __launch_bounds__(256) void knn_kernel(const float* __restrict__ xyz2)
{
    __shared__ float4 spt[N1];            // 32KB
    __shared__ int    cst[NCELL + 1];

    const int b = blockIdx.y;
    for (int i = threadIdx.x; i < N1; i += 256)
        spt[i] = g_sxyz[b * N1 + i];
    for (int i = threadIdx.x; i < NCELL + 1; i += 256)
        cst[i] = g_cellstart[b * (NCELL + 1) + i];
    __syncthreads();

    const int q = b * N2 + blockIdx.x * 256 + threadIdx.x;
    const float qx = xyz2[q * 3 + 0];
    const float qy = xyz2[q * 3 + 1];
    const float qz = xyz2[q * 3 + 2];
    const int cx = cellof(qx), cy = cellof(qy), cz = cellof(qz);

    float dk[NSAMP];
    int   ik[NSAMP];
    #pragma unroll
    for (int p = 0; p < NSAMP; ++p) { dk[p] = 3.4e38f; ik[p] = 0; }

    auto scan_run = [&](int rowbase, int xa, int xb) {
        const int pe = cst[rowbase + xb + 1];
        for (int p = cst[rowbase + xa]; p < pe; ++p) {
            const float4 P = spt[p];
            const float dx = qx - P.x;
            const float dy = qy - P.y;
            const float dz = qz - P.z;
            const float d2 = fmaf(dx, dx, fmaf(dy, dy, dz * dz));
            if (d2 < dk[NSAMP - 1]) {
                dk[NSAMP - 1] = d2;
                ik[NSAMP - 1] = __float_as_int(P.w);
                #pragma unroll
                for (int s = NSAMP - 1; s > 0; --s) {
                    if (dk[s] < dk[s - 1]) {
                        float td = dk[s]; dk[s] = dk[s-1]; dk[s-1] = td;
                        int   ti = ik[s]; ik[s] = ik[s-1]; ik[s-1] = ti;
                    }
                }
            }
        }
    };

    for (int R = 0; R < GRID; ++R) {
        const int zlo = max(cz - R, 0), zhi = min(cz + R, GRID - 1);
        const int ylo = max(cy - R, 0), yhi = min(cy + R, GRID - 1);
        const int xlo = max(cx - R, 0), xhi = min(cx + R, GRID - 1);
        for (int z = zlo; z <= zhi; ++z) {
            const int az = abs(z - cz);
            for (int y = ylo; y <= yhi; ++y) {
                const int ay = abs(y - cy);
                const int rowbase = (z << 6) | (y << 3);
                if (az == R || ay == R) {
                    scan_run(rowbase, xlo, xhi);       // full row in shell
                } else {
                    if (cx - R >= 0)        scan_run(rowbase, cx - R, cx - R);
                    if (cx + R <= GRID - 1) scan_run(rowbase, cx + R, cx + R);
                }
            }
        }
        const float bnd = (float)R * CELLH;
        if (dk[NSAMP - 1] < bnd * bnd) break;
    }

    int* o = g_idx + q * NSAMP;
    #pragma unroll
    for (int p = 0; p < NSAMP; ++p) o[p] = ik[p];
}

// ---------------------------------------------------------------------------
// Kernel 2: weighted aggregation, fp16 output (single array).
// ---------------------------------------------------------------------------
__global__ __launch_bounds__(128) void wf_kernel(
    const float* __restrict__ xyz1, const float* __restrict__ feat1,
    const float* __restrict__ xyz2, const float* __restrict__ kp)
{
    const int wid = threadIdx.x >> 5;
    const int L   = threadIdx.x & 31;
    const int q   = blockIdx.x * 4 + wid;
    const int b   = q >> 13;

    __shared__ float  skp[KP * 3];
    __shared__ float2 sw2[4][NSAMP][KP];

    if (threadIdx.x < KP * 3) skp[threadIdx.x] = kp[threadIdx.x];
    __syncthreads();

    int sid = 0;
    if (L < NSAMP) {
        sid = g_idx[q * NSAMP + L];
        const float rx = xyz1[((size_t)b * N1 + sid) * 3 + 0] - xyz2[q * 3 + 0];
        const float ry = xyz1[((size_t)b * N1 + sid) * 3 + 1] - xyz2[q * 3 + 1];
        const float rz = xyz1[((size_t)b * N1 + sid) * 3 + 2] - xyz2[q * 3 + 2];
        #pragma unroll
        for (int k = 0; k < KP; ++k) {
            float dx = rx - skp[k * 3 + 0];
            float dy = ry - skp[k * 3 + 1];
            float dz = rz - skp[k * 3 + 2];
            float sq = dx * dx + dy * dy + dz * dz;
            float dist = sqrtf(fmaxf(sq, 1e-12f));
            float wt = fmaxf(0.0f, 1.0f - dist / 0.2f);
            sw2[wid][L][k] = make_float2(wt, wt);
        }
    }
    __syncwarp();

    const float* fb = feat1 + (size_t)b * N1 * C1;
    unsigned long long fxy[NSAMP], fzw[NSAMP];
    #pragma unroll
    for (int s = 0; s < NSAMP; ++s) {
        const int is = __shfl_sync(0xffffffffu, sid, s);
        const float4 v = *(const float4*)(fb + (size_t)is * C1 + 4 * L);
        PACKF2(fxy[s], v.x, v.y);
        PACKF2(fzw[s], v.z, v.w);
    }

    unsigned long long a0[KP], a1[KP];
    #pragma unroll
    for (int k = 0; k < KP; ++k) { a0[k] = 0ull; a1[k] = 0ull; }

    #pragma unroll
    for (int s = 0; s < NSAMP; ++s) {
        #pragma unroll
        for (int k = 0; k < KP; ++k) {
            const unsigned long long wp =
                *(const unsigned long long*)&sw2[wid][s][k];
            FFMA2(a0[k], wp, fxy[s]);
            FFMA2(a1[k], wp, fzw[s]);
        }
    }

    const size_t qbase = (size_t)q * KDIM + 4 * L;
    #pragma unroll
    for (int k = 0; k < KP; ++k) {
        float vx, vy, vz, vw;
        UNPACKF2(vx, vy, a0[k]);
        UNPACKF2(vz, vw, a1[k]);
        __half2 h0 = __floats2half2_rn(vx, vy);
        __half2 h1 = __floats2half2_rn(vz, vw);
        uint2 st;
        st.x = *(const uint32_t*)&h0;
        st.y = *(const uint32_t*)&h1;
        *(uint2*)(g_a + qbase + k * C1) = st;
    }
}

// ---------------------------------------------------------------------------
// Kernel 3: mma.sync pure fp16 GEMM (1 product), fused concat.
// M=32768 (128 CTAs of 256 rows), N=128, K=1920 in 60 chunks of 32 (64B rows).
// 8 warps in 4(M)x2(N): warp tile 64x64. 4-stage cp.async (24KB/stage).
// ---------------------------------------------------------------------------
#define A_SUB       16384               // 256 rows x 64B
#define B_SUB       8192                // 128 rows x 64B
#define STAGE_BYTES (A_SUB + B_SUB)           // 24KB
#define NSTAGE      4
#define GEMM_SMEM   (NSTAGE * STAGE_BYTES)    // 96KB

__global__ __launch_bounds__(256, 1)
void gemm_kernel(const float* __restrict__ feat2, float* __restrict__ out)
{
    extern __shared__ __align__(1024) char dsmem[];

    const int tid = threadIdx.x;
    const int wid = tid >> 5;
    const int L   = tid & 31;
    const int m0  = blockIdx.x * 256;
    const int wm  = wid & 3;              // 0..3 (M, 64 rows each)
    const int wn  = wid >> 2;             // 0..1 (N, 64 cols each)

    const uint32_t base = smem_u32(dsmem);

    const char* srcA = (const char*)g_a + (size_t)m0 * (KDIM * 2);
    const char* srcB = (const char*)g_b;

    // one stage: A 256 rows x 4 quads (1024), B 128 rows x 4 quads (512)
    auto load_stage = [&](int chunk, int buf) {
        const uint32_t sbase = base + buf * STAGE_BYTES;
        #pragma unroll
        for (int v = 0; v < 4; ++v) {
            int idx = v * 256 + tid;          // 0..1023
            int row = idx >> 2;               // 0..255
            int kb  = (idx & 3) << 4;         // 0..48
            const char* g = srcA + (size_t)row * (KDIM * 2) + chunk * 64 + kb;
            uint32_t sa = sbase + sw64(row, kb);
            asm volatile("cp.async.cg.shared.global [%0], [%1], 16;"
                         :: "r"(sa), "l"(g));
        }
        #pragma unroll
        for (int v = 0; v < 2; ++v) {
            int idx = v * 256 + tid;          // 0..511
            int row = idx >> 2;               // 0..127
            int kb  = (idx & 3) << 4;
            const char* g = srcB + (size_t)row * (KDIM * 2) + chunk * 64 + kb;
            uint32_t sa = sbase + A_SUB + sw64(row, kb);
            asm volatile("cp.async.cg.shared.global [%0], [%1], 16;"
                         :: "r"(sa), "l"(g));
        }
        asm volatile("cp.async.commit_group;" ::: "memory");
    };

    // ldmatrix per-thread offsets (64B rows, quad swizzle)
    int aRow = wm * 64 + (L & 15);                  // + mt*16
    int aKb  = (L >> 4) * 16;                       // 0 or 16
    int bRow = wn * 64 + ((L >> 4) << 3) + (L & 7); // + ng*16
    int bKb  = ((L >> 3) & 1) * 16;

    uint32_t aOff[4], aXor[4];
    #pragma unroll
    for (int mt = 0; mt < 4; ++mt) {
        int r = aRow + mt * 16;
        aOff[mt] = r * 64;
        aXor[mt] = ((r >> 1) & 3) << 4;
    }
    uint32_t bOff[4], bXor[4];
    #pragma unroll
    for (int ng = 0; ng < 4; ++ng) {
        int r = bRow + ng * 16;
        bOff[ng] = r * 64;
        bXor[ng] = ((r >> 1) & 3) << 4;
    }

    float acc[4][8][4];
    #pragma unroll
    for (int i = 0; i < 4; ++i)
        #pragma unroll
        for (int j = 0; j < 8; ++j)
            #pragma unroll
            for (int k = 0; k < 4; ++k) acc[i][j][k] = 0.0f;

    load_stage(0, 0);
    load_stage(1, 1);
    load_stage(2, 2);

    // fused concat: copy feat2 rows [m0, m0+256) into out[:,128:192)
    {
        const float* f2 = feat2 + (size_t)m0 * C2;
        float* o2 = out + (size_t)m0 * OUTC + FOUT;
        #pragma unroll
        for (int i = 0; i < 16; ++i) {
            int v = i * 256 + tid;            // 0..4095
            int row = v >> 4;
            int j   = v & 15;
            float4 t = *(const float4*)(f2 + (size_t)row * C2 + j * 4);
            *(float4*)(o2 + (size_t)row * OUTC + j * 4) = t;
        }
    }

    for (int i = 0; i < NCHUNK; ++i) {
        const int buf = i & 3;
        if (i + 2 < NCHUNK)
            asm volatile("cp.async.wait_group 2;" ::: "memory");
        else if (i + 1 < NCHUNK)
            asm volatile("cp.async.wait_group 1;" ::: "memory");
        else
            asm volatile("cp.async.wait_group 0;" ::: "memory");
        __syncthreads();

        const uint32_t sb = base + buf * STAGE_BYTES;
        const uint32_t sA = sb;
        const uint32_t sB = sb + A_SUB;

        #pragma unroll
        for (int ks = 0; ks < 2; ++ks) {
            const uint32_t kA = ks * 32 + aKb;
            const uint32_t kB = ks * 32 + bKb;
            uint32_t a[4][4];
            #pragma unroll
            for (int mt = 0; mt < 4; ++mt)
                ldsm4(a[mt], sA + aOff[mt] + (kA ^ aXor[mt]));
            #pragma unroll
            for (int ng = 0; ng < 4; ++ng) {
                uint32_t bb[4];
                ldsm4(bb, sB + bOff[ng] + (kB ^ bXor[ng]));
                #pragma unroll
                for (int mt = 0; mt < 4; ++mt) {
                    mma16816h(acc[mt][ng * 2 + 0], a[mt], &bb[0]);
                    mma16816h(acc[mt][ng * 2 + 1], a[mt], &bb[2]);
                }
            }
        }

        if (i + 3 < NCHUNK) load_stage(i + 3, (i + 3) & 3);
    }

    #pragma unroll
    for (int mt = 0; mt < 4; ++mt) {
        #pragma unroll
        for (int nt = 0; nt < 8; ++nt) {
            const float* c = acc[mt][nt];
            int row = m0 + wm * 64 + mt * 16 + (L >> 2);
            int col = wn * 64 + nt * 8 + (L & 3) * 2;
            float2 v0, v1;
            v0.x = fmaxf(c[0], 0.0f); v0.y = fmaxf(c[1], 0.0f);
            v1.x = fmaxf(c[2], 0.0f); v1.y = fmaxf(c[3], 0.0f);
            *(float2*)(out + (size_t)row * OUTC + col)       = v0;
            *(float2*)(out + (size_t)(row + 8) * OUTC + col) = v1;
        }
    }
}

// ---------------------------------------------------------------------------
// Launch
// ---------------------------------------------------------------------------
extern "C" void kernel_launch(void* const* d_in, const int* in_sizes, int n_in,
                              void* d_out, int out_size)
{
    const float* xyz1  = (const float*)d_in[0];
    const float* feat1 = (const float*)d_in[1];
    const float* xyz2  = (const float*)d_in[2];
    const float* feat2 = (const float*)d_in[3];
    const float* kp    = (const float*)d_in[4];
    const float* W     = (const float*)d_in[5];
    float* out = (float*)d_out;

    cudaFuncSetAttribute(gemm_kernel,
                         cudaFuncAttributeMaxDynamicSharedMemorySize, GEMM_SMEM);

    prep_kernel<<<BATCH + (KDIM * FOUT) / 512, 512>>>(xyz1, W);
    knn_kernel<<<dim3(N2 / 256, BATCH), 256>>>(xyz2);
    wf_kernel<<<NQ / 4, 128>>>(xyz1, feat1, xyz2, kp);
    gemm_kernel<<<NQ / 256, 256, GEMM_SMEM>>>(feat2, out);
}

// round 14
// speedup vs baseline: 1.6367x; 1.1766x over previous
#include <cuda_runtime.h>
#include <cuda_fp16.h>
#include <cstdint>

// ---------------------------------------------------------------------------
// Problem constants
// ---------------------------------------------------------------------------
#define BATCH   4
#define N1      2048
#define N2      8192
#define C1      128
#define C2      64
#define KP      15
#define FOUT    128
#define NSAMP   16
#define NQ      (BATCH * N2)          // 32768 queries
#define KDIM    (KP * C1)             // 1920
#define OUTC    (FOUT + C2)           // 192
#define NCHUNK  (KDIM / 32)           // 60 K-chunks of 32 fp16 (64B rows)

#define GRID    8                     // 8x8x8 spatial bins
#define NCELL   (GRID * GRID * GRID)  // 512
#define CELLH   0.125f

// Scratch (device globals)
__device__ int     g_idx[NQ * NSAMP];
__device__ float4  g_sxyz[BATCH * N1];        // binned points (x,y,z,idx)
__device__ int     g_cellstart[BATCH * (NCELL + 1)];
__device__ int     g_qorder[NQ];              // queries in cell-sorted order
__device__ __half  g_a[(size_t)NQ * KDIM];    // wf in fp16, row-major (q, kc)
__device__ __half  g_b[(size_t)FOUT * KDIM];  // W^T in fp16, (f, kc)

// ---------------------------------------------------------------------------
// Helpers
// ---------------------------------------------------------------------------
__device__ __forceinline__ uint32_t smem_u32(const void* p) {
    uint32_t a;
    asm("{ .reg .u64 t; cvta.to.shared.u64 t, %1; cvt.u32.u64 %0, t; }"
        : "=r"(a) : "l"(p));
    return a;
}
__device__ __forceinline__ void ldsm4(uint32_t* r, uint32_t addr) {
    asm volatile("ldmatrix.sync.aligned.m8n8.x4.shared.b16 {%0,%1,%2,%3}, [%4];"
                 : "=r"(r[0]), "=r"(r[1]), "=r"(r[2]), "=r"(r[3]) : "r"(addr));
}
__device__ __forceinline__ void mma16816h(float* c, const uint32_t* a,
                                          const uint32_t* b) {
    asm volatile(
        "mma.sync.aligned.m16n8k16.row.col.f32.f16.f16.f32 "
        "{%0,%1,%2,%3}, {%4,%5,%6,%7}, {%8,%9}, {%0,%1,%2,%3};"
        : "+f"(c[0]), "+f"(c[1]), "+f"(c[2]), "+f"(c[3])
        : "r"(a[0]), "r"(a[1]), "r"(a[2]), "r"(a[3]), "r"(b[0]), "r"(b[1]));
}
__device__ __forceinline__ int cellof(float x) {
    int c = (int)(x * (float)GRID);
    return min(GRID - 1, max(0, c));
}

// packed f32x2 (sm_100+ PTX, base family feature)
#define FFMA2(acc, a, b) \
    asm("fma.rn.f32x2 %0, %1, %2, %0;" : "+l"(acc) : "l"(a), "l"(b))
#define PACKF2(out, lo, hi) \
    asm("mov.b64 %0, {%1, %2};" : "=l"(out) : "f"(lo), "f"(hi))
#define UNPACKF2(lo, hi, in) \
    asm("mov.b64 {%0, %1}, %2;" : "=f"(lo), "=f"(hi) : "l"(in))

// 64B-row smem swizzle: quad (16B) index XORed with ((row>>1)&3)
__device__ __forceinline__ uint32_t sw64(int row, int kb) {
    return row * 64 + (kb ^ (((row >> 1) & 3) << 4));
}

// ---------------------------------------------------------------------------
// Kernel 0: prep.
//   blocks [0, BATCH):          bin xyz1 points into cells
//   blocks [BATCH, 2*BATCH):    bin xyz2 queries (cell-sorted order only)
//   blocks [2*BATCH, ...):      W fp16 transpose
// ---------------------------------------------------------------------------
__global__ __launch_bounds__(512) void prep_kernel(
    const float* __restrict__ xyz1, const float* __restrict__ xyz2,
    const float* __restrict__ W)
{
    const int t = threadIdx.x;

    if (blockIdx.x >= 2 * BATCH) {
        const int i = (blockIdx.x - 2 * BATCH) * 512 + t;
        const int kc = i / FOUT;
        const int f  = i % FOUT;
        g_b[(size_t)f * KDIM + kc] = __float2half_rn(W[i]);
        return;
    }

    __shared__ int cnt[NCELL];
    __shared__ int sscan[NCELL];
    __shared__ int cursor[NCELL];

    cnt[t] = 0;
    __syncthreads();

    if (blockIdx.x < BATCH) {
        // ---- bin xyz1 points ----
        const int b = blockIdx.x;
        float px[N1 / 512], py[N1 / 512], pz[N1 / 512];
        int   cl[N1 / 512];
        #pragma unroll
        for (int k = 0; k < N1 / 512; ++k) {
            const int i = t + k * 512;
            px[k] = xyz1[((size_t)b * N1 + i) * 3 + 0];
            py[k] = xyz1[((size_t)b * N1 + i) * 3 + 1];
            pz[k] = xyz1[((size_t)b * N1 + i) * 3 + 2];
            cl[k] = (cellof(pz[k]) << 6) | (cellof(py[k]) << 3) | cellof(px[k]);
            atomicAdd(&cnt[cl[k]], 1);
        }
        __syncthreads();

        sscan[t] = cnt[t];
        __syncthreads();
        #pragma unroll
        for (int off = 1; off < NCELL; off <<= 1) {
            int add = (t >= off) ? sscan[t - off] : 0;
            __syncthreads();
            sscan[t] += add;
            __syncthreads();
        }
        const int excl = sscan[t] - cnt[t];
        g_cellstart[b * (NCELL + 1) + t] = excl;
        if (t == NCELL - 1) g_cellstart[b * (NCELL + 1) + NCELL] = N1;
        cursor[t] = excl;
        __syncthreads();

        #pragma unroll
        for (int k = 0; k < N1 / 512; ++k) {
            const int i = t + k * 512;
            const int pos = atomicAdd(&cursor[cl[k]], 1);
            g_sxyz[b * N1 + pos] =
                make_float4(px[k], py[k], pz[k], __int_as_float(i));
        }
    } else {
        // ---- bin xyz2 queries: emit cell-sorted query order ----
        const int b = blockIdx.x - BATCH;
        int cl[N2 / 512];
        #pragma unroll
        for (int k = 0; k < N2 / 512; ++k) {
            const int i = t + k * 512;
            const float x = xyz2[((size_t)b * N2 + i) * 3 + 0];
            const float y = xyz2[((size_t)b * N2 + i) * 3 + 1];
            const float z = xyz2[((size_t)b * N2 + i) * 3 + 2];
            cl[k] = (cellof(z) << 6) | (cellof(y) << 3) | cellof(x);
            atomicAdd(&cnt[cl[k]], 1);
        }
        __syncthreads();

        sscan[t] = cnt[t];
        __syncthreads();
        #pragma unroll
        for (int off = 1; off < NCELL; off <<= 1) {
            int add = (t >= off) ? sscan[t - off] : 0;
            __syncthreads();
            sscan[t] += add;
            __syncthreads();
        }
        cursor[t] = sscan[t] - cnt[t];
        __syncthreads();

        #pragma unroll
        for (int k = 0; k < N2 / 512; ++k) {
            const int i = t + k * 512;
            const int pos = atomicAdd(&cursor[cl[k]], 1);
            g_qorder[b * N2 + pos] = i;
        }
    }
}

// ---------------------------------------------------------------------------
// Kernel 1: kNN via expanding Chebyshev shells, contiguous row-run scans.
// Threads process queries in cell-sorted order: warp-uniform cell walks,
// broadcast smem loads. Output written to the original query slot.
// ---------------------------------------------------------------------------
__global__ __launch_bounds__(256) void knn_kernel(const float* __restrict__ xyz2)
{
    __shared__ float4 spt[N1];            // 32KB
    __shared__ int    cst[NCELL + 1];

    const int b = blockIdx.y;
    for (int i = threadIdx.x; i < N1; i += 256)
        spt[i] = g_sxyz[b * N1 + i];
    for (int i = threadIdx.x; i < NCELL + 1; i += 256)
        cst[i] = g_cellstart[b * (NCELL + 1) + i];
    __syncthreads();

    const int qq = g_qorder[b * N2 + blockIdx.x * 256 + threadIdx.x];
    const size_t qg = (size_t)b * N2 + qq;
    const float qx = xyz2[qg * 3 + 0];
    const float qy = xyz2[qg * 3 + 1];
    const float qz = xyz2[qg * 3 + 2];
    const int cx = cellof(qx), cy = cellof(qy), cz = cellof(qz);

    float dk[NSAMP];
    int   ik[NSAMP];
    #pragma unroll
    for (int p = 0; p < NSAMP; ++p) { dk[p] = 3.4e38f; ik[p] = 0; }

    auto scan_run = [&](int rowbase, int xa, int xb) {
        const int pe = cst[rowbase + xb + 1];
        for (int p = cst[rowbase + xa]; p < pe; ++p) {
            const float4 P = spt[p];
            const float dx = qx - P.x;
            const float dy = qy - P.y;
            const float dz = qz - P.z;
            const float d2 = fmaf(dx, dx, fmaf(dy, dy, dz * dz));
            if (d2 < dk[NSAMP - 1]) {
                dk[NSAMP - 1] = d2;
                ik[NSAMP - 1] = __float_as_int(P.w);
                #pragma unroll
                for (int s = NSAMP - 1; s > 0; --s) {
                    if (dk[s] < dk[s - 1]) {
                        float td = dk[s]; dk[s] = dk[s-1]; dk[s-1] = td;
                        int   ti = ik[s]; ik[s] = ik[s-1]; ik[s-1] = ti;
                    }
                }
            }
        }
    };

    for (int R = 0; R < GRID; ++R) {
        const int zlo = max(cz - R, 0), zhi = min(cz + R, GRID - 1);
        const int ylo = max(cy - R, 0), yhi = min(cy + R, GRID - 1);
        const int xlo = max(cx - R, 0), xhi = min(cx + R, GRID - 1);
        for (int z = zlo; z <= zhi; ++z) {
            const int az = abs(z - cz);
            for (int y = ylo; y <= yhi; ++y) {
                const int ay = abs(y - cy);
                const int rowbase = (z << 6) | (y << 3);
                if (az == R || ay == R) {
                    scan_run(rowbase, xlo, xhi);       // full row in shell
                } else {
                    if (cx - R >= 0)        scan_run(rowbase, cx - R, cx - R);
                    if (cx + R <= GRID - 1) scan_run(rowbase, cx + R, cx + R);
                }
            }
        }
        const float bnd = (float)R * CELLH;
        if (dk[NSAMP - 1] < bnd * bnd) break;
    }

    int* o = g_idx + qg * NSAMP;
    #pragma unroll
    for (int p = 0; p < NSAMP; ++p) o[p] = ik[p];
}

// ---------------------------------------------------------------------------
// Kernel 2: weighted aggregation, fp16 output (single array). Unchanged.
// ---------------------------------------------------------------------------
__global__ __launch_bounds__(128) void wf_kernel(
    const float* __restrict__ xyz1, const float* __restrict__ feat1,
    const float* __restrict__ xyz2, const float* __restrict__ kp)
{
    const int wid = threadIdx.x >> 5;
    const int L   = threadIdx.x & 31;
    const int q   = blockIdx.x * 4 + wid;
    const int b   = q >> 13;

    __shared__ float  skp[KP * 3];
    __shared__ float2 sw2[4][NSAMP][KP];

    if (threadIdx.x < KP * 3) skp[threadIdx.x] = kp[threadIdx.x];
    __syncthreads();

    int sid = 0;
    if (L < NSAMP) {
        sid = g_idx[q * NSAMP + L];
        const float rx = xyz1[((size_t)b * N1 + sid) * 3 + 0] - xyz2[q * 3 + 0];
        const float ry = xyz1[((size_t)b * N1 + sid) * 3 + 1] - xyz2[q * 3 + 1];
        const float rz = xyz1[((size_t)b * N1 + sid) * 3 + 2] - xyz2[q * 3 + 2];
        #pragma unroll
        for (int k = 0; k < KP; ++k) {
            float dx = rx - skp[k * 3 + 0];
            float dy = ry - skp[k * 3 + 1];
            float dz = rz - skp[k * 3 + 2];
            float sq = dx * dx + dy * dy + dz * dz;
            float dist = sqrtf(fmaxf(sq, 1e-12f));
            float wt = fmaxf(0.0f, 1.0f - dist / 0.2f);
            sw2[wid][L][k] = make_float2(wt, wt);
        }
    }
    __syncwarp();

    const float* fb = feat1 + (size_t)b * N1 * C1;
    unsigned long long fxy[NSAMP], fzw[NSAMP];
    #pragma unroll
    for (int s = 0; s < NSAMP; ++s) {
        const int is = __shfl_sync(0xffffffffu, sid, s);
        const float4 v = *(const float4*)(fb + (size_t)is * C1 + 4 * L);
        PACKF2(fxy[s], v.x, v.y);
        PACKF2(fzw[s], v.z, v.w);
    }

    unsigned long long a0[KP], a1[KP];
    #pragma unroll
    for (int k = 0; k < KP; ++k) { a0[k] = 0ull; a1[k] = 0ull; }

    #pragma unroll
    for (int s = 0; s < NSAMP; ++s) {
        #pragma unroll
        for (int k = 0; k < KP; ++k) {
            const unsigned long long wp =
                *(const unsigned long long*)&sw2[wid][s][k];
            FFMA2(a0[k], wp, fxy[s]);
            FFMA2(a1[k], wp, fzw[s]);
        }
    }

    const size_t qbase = (size_t)q * KDIM + 4 * L;
    #pragma unroll
    for (int k = 0; k < KP; ++k) {
        float vx, vy, vz, vw;
        UNPACKF2(vx, vy, a0[k]);
        UNPACKF2(vz, vw, a1[k]);
        __half2 h0 = __floats2half2_rn(vx, vy);
        __half2 h1 = __floats2half2_rn(vz, vw);
        uint2 st;
        st.x = *(const uint32_t*)&h0;
        st.y = *(const uint32_t*)&h1;
        *(uint2*)(g_a + qbase + k * C1) = st;
    }
}

// ---------------------------------------------------------------------------
// Kernel 3: mma.sync pure fp16 GEMM (1 product), fused concat. Unchanged.
// ---------------------------------------------------------------------------
#define A_SUB       16384               // 256 rows x 64B
#define B_SUB       8192                // 128 rows x 64B
#define STAGE_BYTES (A_SUB + B_SUB)           // 24KB
#define NSTAGE      4
#define GEMM_SMEM   (NSTAGE * STAGE_BYTES)    // 96KB

__global__ __launch_bounds__(256, 1)
void gemm_kernel(const float* __restrict__ feat2, float* __restrict__ out)
{
    extern __shared__ __align__(1024) char dsmem[];

    const int tid = threadIdx.x;
    const int wid = tid >> 5;
    const int L   = tid & 31;
    const int m0  = blockIdx.x * 256;
    const int wm  = wid & 3;              // 0..3 (M, 64 rows each)
    const int wn  = wid >> 2;             // 0..1 (N, 64 cols each)

    const uint32_t base = smem_u32(dsmem);

    const char* srcA = (const char*)g_a + (size_t)m0 * (KDIM * 2);
    const char* srcB = (const char*)g_b;

    auto load_stage = [&](int chunk, int buf) {
        const uint32_t sbase = base + buf * STAGE_BYTES;
        #pragma unroll
        for (int v = 0; v < 4; ++v) {
            int idx = v * 256 + tid;          // 0..1023
            int row = idx >> 2;               // 0..255
            int kb  = (idx & 3) << 4;         // 0..48
            const char* g = srcA + (size_t)row * (KDIM * 2) + chunk * 64 + kb;
            uint32_t sa = sbase + sw64(row, kb);
            asm volatile("cp.async.cg.shared.global [%0], [%1], 16;"
                         :: "r"(sa), "l"(g));
        }
        #pragma unroll
        for (int v = 0; v < 2; ++v) {
            int idx = v * 256 + tid;          // 0..511
            int row = idx >> 2;               // 0..127
            int kb  = (idx & 3) << 4;
            const char* g = srcB + (size_t)row * (KDIM * 2) + chunk * 64 + kb;
            uint32_t sa = sbase + A_SUB + sw64(row, kb);
            asm volatile("cp.async.cg.shared.global [%0], [%1], 16;"
                         :: "r"(sa), "l"(g));
        }
        asm volatile("cp.async.commit_group;" ::: "memory");
    };

    int aRow = wm * 64 + (L & 15);                  // + mt*16
    int aKb  = (L >> 4) * 16;                       // 0 or 16
    int bRow = wn * 64 + ((L >> 4) << 3) + (L & 7); // + ng*16
    int bKb  = ((L >> 3) & 1) * 16;

    uint32_t aOff[4], aXor[4];
    #pragma unroll
    for (int mt = 0; mt < 4; ++mt) {
        int r = aRow + mt * 16;
        aOff[mt] = r * 64;
        aXor[mt] = ((r >> 1) & 3) << 4;
    }
    uint32_t bOff[4], bXor[4];
    #pragma unroll
    for (int ng = 0; ng < 4; ++ng) {
        int r = bRow + ng * 16;
        bOff[ng] = r * 64;
        bXor[ng] = ((r >> 1) & 3) << 4;
    }

    float acc[4][8][4];
    #pragma unroll
    for (int i = 0; i < 4; ++i)
        #pragma unroll
        for (int j = 0; j < 8; ++j)
            #pragma unroll
            for (int k = 0; k < 4; ++k) acc[i][j][k] = 0.0f;

    load_stage(0, 0);
    load_stage(1, 1);
    load_stage(2, 2);

    // fused concat: copy feat2 rows [m0, m0+256) into out[:,128:192)
    {
        const float* f2 = feat2 + (size_t)m0 * C2;
        float* o2 = out + (size_t)m0 * OUTC + FOUT;
        #pragma unroll
        for (int i = 0; i < 16; ++i) {
            int v = i * 256 + tid;            // 0..4095
            int row = v >> 4;
            int j   = v & 15;
            float4 t = *(const float4*)(f2 + (size_t)row * C2 + j * 4);
            *(float4*)(o2 + (size_t)row * OUTC + j * 4) = t;
        }
    }

    for (int i = 0; i < NCHUNK; ++i) {
        const int buf = i & 3;
        if (i + 2 < NCHUNK)
            asm volatile("cp.async.wait_group 2;" ::: "memory");
        else if (i + 1 < NCHUNK)
            asm volatile("cp.async.wait_group 1;" ::: "memory");
        else
            asm volatile("cp.async.wait_group 0;" ::: "memory");
        __syncthreads();

        const uint32_t sb = base + buf * STAGE_BYTES;
        const uint32_t sA = sb;
        const uint32_t sB = sb + A_SUB;

        #pragma unroll
        for (int ks = 0; ks < 2; ++ks) {
            const uint32_t kA = ks * 32 + aKb;
            const uint32_t kB = ks * 32 + bKb;
            uint32_t a[4][4];
            #pragma unroll
            for (int mt = 0; mt < 4; ++mt)
                ldsm4(a[mt], sA + aOff[mt] + (kA ^ aXor[mt]));
            #pragma unroll
            for (int ng = 0; ng < 4; ++ng) {
                uint32_t bb[4];
                ldsm4(bb, sB + bOff[ng] + (kB ^ bXor[ng]));
                #pragma unroll
                for (int mt = 0; mt < 4; ++mt) {
                    mma16816h(acc[mt][ng * 2 + 0], a[mt], &bb[0]);
                    mma16816h(acc[mt][ng * 2 + 1], a[mt], &bb[2]);
                }
            }
        }

        if (i + 3 < NCHUNK) load_stage(i + 3, (i + 3) & 3);
    }

    #pragma unroll
    for (int mt = 0; mt < 4; ++mt) {
        #pragma unroll
        for (int nt = 0; nt < 8; ++nt) {
            const float* c = acc[mt][nt];
            int row = m0 + wm * 64 + mt * 16 + (L >> 2);
            int col = wn * 64 + nt * 8 + (L & 3) * 2;
            float2 v0, v1;
            v0.x = fmaxf(c[0], 0.0f); v0.y = fmaxf(c[1], 0.0f);
            v1.x = fmaxf(c[2], 0.0f); v1.y = fmaxf(c[3], 0.0f);
            *(float2*)(out + (size_t)row * OUTC + col)       = v0;
            *(float2*)(out + (size_t)(row + 8) * OUTC + col) = v1;
        }
    }
}

// ---------------------------------------------------------------------------
// Launch
// ---------------------------------------------------------------------------
extern "C" void kernel_launch(void* const* d_in, const int* in_sizes, int n_in,
                              void* d_out, int out_size)
{
    const float* xyz1  = (const float*)d_in[0];
    const float* feat1 = (const float*)d_in[1];
    const float* xyz2  = (const float*)d_in[2];
    const float* feat2 = (const float*)d_in[3];
    const float* kp    = (const float*)d_in[4];
    const float* W     = (const float*)d_in[5];
    float* out = (float*)d_out;

    cudaFuncSetAttribute(gemm_kernel,
                         cudaFuncAttributeMaxDynamicSharedMemorySize, GEMM_SMEM);

    prep_kernel<<<2 * BATCH + (KDIM * FOUT) / 512, 512>>>(xyz1, xyz2, W);
    knn_kernel<<<dim3(N2 / 256, BATCH), 256>>>(xyz2);
    wf_kernel<<<NQ / 4, 128>>>(xyz1, feat1, xyz2, kp);
    gemm_kernel<<<NQ / 256, 256, GEMM_SMEM>>>(feat2, out);
}

// round 15
// speedup vs baseline: 1.6621x; 1.0156x over previous
#include <cuda_runtime.h>
#include <cuda_fp16.h>
#include <cstdint>

// ---------------------------------------------------------------------------
// Problem constants
// ---------------------------------------------------------------------------
#define BATCH   4
#define N1      2048
#define N2      8192
#define C1      128
#define C2      64
#define KP      15
#define FOUT    128
#define NSAMP   16
#define NQ      (BATCH * N2)          // 32768 queries
#define KDIM    (KP * C1)             // 1920
#define OUTC    (FOUT + C2)           // 192
#define NCHUNK  (KDIM / 32)           // 60 K-chunks of 32 fp16 (64B rows)

#define GRID    8                     // 8x8x8 spatial bins
#define NCELL   (GRID * GRID * GRID)  // 512
#define CELLH   0.125f

// Scratch (device globals)
__device__ int     g_idx[NQ * NSAMP];
__device__ float4  g_sxyz[BATCH * N1];        // binned points (x,y,z,idx)
__device__ int     g_cellstart[BATCH * (NCELL + 1)];
__device__ int     g_qorder[NQ];              // queries in cell-sorted order
__device__ __half  g_a[(size_t)NQ * KDIM];    // wf in fp16, row-major (q, kc)
__device__ __half  g_b[(size_t)FOUT * KDIM];  // W^T in fp16, (f, kc)

// ---------------------------------------------------------------------------
// Helpers
// ---------------------------------------------------------------------------
__device__ __forceinline__ uint32_t smem_u32(const void* p) {
    uint32_t a;
    asm("{ .reg .u64 t; cvta.to.shared.u64 t, %1; cvt.u32.u64 %0, t; }"
        : "=r"(a) : "l"(p));
    return a;
}
__device__ __forceinline__ void ldsm4(uint32_t* r, uint32_t addr) {
    asm volatile("ldmatrix.sync.aligned.m8n8.x4.shared.b16 {%0,%1,%2,%3}, [%4];"
                 : "=r"(r[0]), "=r"(r[1]), "=r"(r[2]), "=r"(r[3]) : "r"(addr));
}
__device__ __forceinline__ void mma16816h(float* c, const uint32_t* a,
                                          const uint32_t* b) {
    asm volatile(
        "mma.sync.aligned.m16n8k16.row.col.f32.f16.f16.f32 "
        "{%0,%1,%2,%3}, {%4,%5,%6,%7}, {%8,%9}, {%0,%1,%2,%3};"
        : "+f"(c[0]), "+f"(c[1]), "+f"(c[2]), "+f"(c[3])
        : "r"(a[0]), "r"(a[1]), "r"(a[2]), "r"(a[3]), "r"(b[0]), "r"(b[1]));
}
__device__ __forceinline__ int cellof(float x) {
    int c = (int)(x * (float)GRID);
    return min(GRID - 1, max(0, c));
}

// packed f32x2 (sm_100+ PTX, base family feature)
#define FFMA2(acc, a, b) \
    asm("fma.rn.f32x2 %0, %1, %2, %0;" : "+l"(acc) : "l"(a), "l"(b))
#define PACKF2(out, lo, hi) \
    asm("mov.b64 %0, {%1, %2};" : "=l"(out) : "f"(lo), "f"(hi))
#define UNPACKF2(lo, hi, in) \
    asm("mov.b64 {%0, %1}, %2;" : "=f"(lo), "=f"(hi) : "l"(in))

// 64B-row smem swizzle: quad (16B) index XORed with ((row>>1)&3)
__device__ __forceinline__ uint32_t sw64(int row, int kb) {
    return row * 64 + (kb ^ (((row >> 1) & 3) << 4));
}

// ---------------------------------------------------------------------------
// Kernel 0: prep.
//   blocks [0, BATCH):          bin xyz1 points into cells
//   blocks [BATCH, 2*BATCH):    bin xyz2 queries (cell-sorted order only)
//   blocks [2*BATCH, ...):      W fp16 transpose
// ---------------------------------------------------------------------------
__global__ __launch_bounds__(512) void prep_kernel(
    const float* __restrict__ xyz1, const float* __restrict__ xyz2,
    const float* __restrict__ W)
{
    const int t = threadIdx.x;

    if (blockIdx.x >= 2 * BATCH) {
        const int i = (blockIdx.x - 2 * BATCH) * 512 + t;
        const int kc = i / FOUT;
        const int f  = i % FOUT;
        g_b[(size_t)f * KDIM + kc] = __float2half_rn(W[i]);
        return;
    }

    __shared__ int cnt[NCELL];
    __shared__ int sscan[NCELL];
    __shared__ int cursor[NCELL];

    cnt[t] = 0;
    __syncthreads();

    if (blockIdx.x < BATCH) {
        // ---- bin xyz1 points ----
        const int b = blockIdx.x;
        float px[N1 / 512], py[N1 / 512], pz[N1 / 512];
        int   cl[N1 / 512];
        #pragma unroll
        for (int k = 0; k < N1 / 512; ++k) {
            const int i = t + k * 512;
            px[k] = xyz1[((size_t)b * N1 + i) * 3 + 0];
            py[k] = xyz1[((size_t)b * N1 + i) * 3 + 1];
            pz[k] = xyz1[((size_t)b * N1 + i) * 3 + 2];
            cl[k] = (cellof(pz[k]) << 6) | (cellof(py[k]) << 3) | cellof(px[k]);
            atomicAdd(&cnt[cl[k]], 1);
        }
        __syncthreads();

        sscan[t] = cnt[t];
        __syncthreads();
        #pragma unroll
        for (int off = 1; off < NCELL; off <<= 1) {
            int add = (t >= off) ? sscan[t - off] : 0;
            __syncthreads();
            sscan[t] += add;
            __syncthreads();
        }
        const int excl = sscan[t] - cnt[t];
        g_cellstart[b * (NCELL + 1) + t] = excl;
        if (t == NCELL - 1) g_cellstart[b * (NCELL + 1) + NCELL] = N1;
        cursor[t] = excl;
        __syncthreads();

        #pragma unroll
        for (int k = 0; k < N1 / 512; ++k) {
            const int i = t + k * 512;
            const int pos = atomicAdd(&cursor[cl[k]], 1);
            g_sxyz[b * N1 + pos] =
                make_float4(px[k], py[k], pz[k], __int_as_float(i));
        }
    } else {
        // ---- bin xyz2 queries: emit cell-sorted query order ----
        const int b = blockIdx.x - BATCH;
        int cl[N2 / 512];
        #pragma unroll
        for (int k = 0; k < N2 / 512; ++k) {
            const int i = t + k * 512;
            const float x = xyz2[((size_t)b * N2 + i) * 3 + 0];
            const float y = xyz2[((size_t)b * N2 + i) * 3 + 1];
            const float z = xyz2[((size_t)b * N2 + i) * 3 + 2];
            cl[k] = (cellof(z) << 6) | (cellof(y) << 3) | cellof(x);
            atomicAdd(&cnt[cl[k]], 1);
        }
        __syncthreads();

        sscan[t] = cnt[t];
        __syncthreads();
        #pragma unroll
        for (int off = 1; off < NCELL; off <<= 1) {
            int add = (t >= off) ? sscan[t - off] : 0;
            __syncthreads();
            sscan[t] += add;
            __syncthreads();
        }
        cursor[t] = sscan[t] - cnt[t];
        __syncthreads();

        #pragma unroll
        for (int k = 0; k < N2 / 512; ++k) {
            const int i = t + k * 512;
            const int pos = atomicAdd(&cursor[cl[k]], 1);
            g_qorder[b * N2 + pos] = i;
        }
    }
}

// ---------------------------------------------------------------------------
// Kernel 1: kNN via expanding Chebyshev shells, contiguous row-run scans.
// Cell-sorted query order; output to the original query slot.
// ---------------------------------------------------------------------------
__global__ __launch_bounds__(256) void knn_kernel(const float* __restrict__ xyz2)
{
    __shared__ float4 spt[N1];            // 32KB
    __shared__ int    cst[NCELL + 1];

    const int b = blockIdx.y;
    for (int i = threadIdx.x; i < N1; i += 256)
        spt[i] = g_sxyz[b * N1 + i];
    for (int i = threadIdx.x; i < NCELL + 1; i += 256)
        cst[i] = g_cellstart[b * (NCELL + 1) + i];
    __syncthreads();

    const int qq = g_qorder[b * N2 + blockIdx.x * 256 + threadIdx.x];
    const size_t qg = (size_t)b * N2 + qq;
    const float qx = xyz2[qg * 3 + 0];
    const float qy = xyz2[qg * 3 + 1];
    const float qz = xyz2[qg * 3 + 2];
    const int cx = cellof(qx), cy = cellof(qy), cz = cellof(qz);

    float dk[NSAMP];
    int   ik[NSAMP];
    #pragma unroll
    for (int p = 0; p < NSAMP; ++p) { dk[p] = 3.4e38f; ik[p] = 0; }

    auto scan_run = [&](int rowbase, int xa, int xb) {
        const int pe = cst[rowbase + xb + 1];
        for (int p = cst[rowbase + xa]; p < pe; ++p) {
            const float4 P = spt[p];
            const float dx = qx - P.x;
            const float dy = qy - P.y;
            const float dz = qz - P.z;
            const float d2 = fmaf(dx, dx, fmaf(dy, dy, dz * dz));
            if (d2 < dk[NSAMP - 1]) {
                dk[NSAMP - 1] = d2;
                ik[NSAMP - 1] = __float_as_int(P.w);
                #pragma unroll
                for (int s = NSAMP - 1; s > 0; --s) {
                    if (dk[s] < dk[s - 1]) {
                        float td = dk[s]; dk[s] = dk[s-1]; dk[s-1] = td;
                        int   ti = ik[s]; ik[s] = ik[s-1]; ik[s-1] = ti;
                    }
                }
            }
        }
    };

    for (int R = 0; R < GRID; ++R) {
        const int zlo = max(cz - R, 0), zhi = min(cz + R, GRID - 1);
        const int ylo = max(cy - R, 0), yhi = min(cy + R, GRID - 1);
        const int xlo = max(cx - R, 0), xhi = min(cx + R, GRID - 1);
        for (int z = zlo; z <= zhi; ++z) {
            const int az = abs(z - cz);
            for (int y = ylo; y <= yhi; ++y) {
                const int ay = abs(y - cy);
                const int rowbase = (z << 6) | (y << 3);
                if (az == R || ay == R) {
                    scan_run(rowbase, xlo, xhi);       // full row in shell
                } else {
                    if (cx - R >= 0)        scan_run(rowbase, cx - R, cx - R);
                    if (cx + R <= GRID - 1) scan_run(rowbase, cx + R, cx + R);
                }
            }
        }
        const float bnd = (float)R * CELLH;
        if (dk[NSAMP - 1] < bnd * bnd) break;
    }

    int* o = g_idx + qg * NSAMP;
    #pragma unroll
    for (int p = 0; p < NSAMP; ++p) o[p] = ik[p];
}

// ---------------------------------------------------------------------------
// Kernel 2: weighted aggregation, fp16 output. Processes queries in
// cell-sorted order (g_qorder) for feat1 gather locality; writes to the
// original query's g_a row.
// ---------------------------------------------------------------------------
__global__ __launch_bounds__(128) void wf_kernel(
    const float* __restrict__ xyz1, const float* __restrict__ feat1,
    const float* __restrict__ xyz2, const float* __restrict__ kp)
{
    const int wid = threadIdx.x >> 5;
    const int L   = threadIdx.x & 31;
    const int qi  = blockIdx.x * 4 + wid;    // sorted index
    const int b   = qi >> 13;

    __shared__ float  skp[KP * 3];
    __shared__ float2 sw2[4][NSAMP][KP];
    __shared__ int    sq[4];

    if (threadIdx.x < KP * 3) skp[threadIdx.x] = kp[threadIdx.x];
    if ((threadIdx.x & 31) == 0)
        sq[wid] = b * N2 + g_qorder[qi];
    __syncthreads();

    const int q = sq[wid];                    // original query id (global)

    int sid = 0;
    if (L < NSAMP) {
        sid = g_idx[(size_t)q * NSAMP + L];
        const float rx = xyz1[((size_t)b * N1 + sid) * 3 + 0] - xyz2[(size_t)q * 3 + 0];
        const float ry = xyz1[((size_t)b * N1 + sid) * 3 + 1] - xyz2[(size_t)q * 3 + 1];
        const float rz = xyz1[((size_t)b * N1 + sid) * 3 + 2] - xyz2[(size_t)q * 3 + 2];
        #pragma unroll
        for (int k = 0; k < KP; ++k) {
            float dx = rx - skp[k * 3 + 0];
            float dy = ry - skp[k * 3 + 1];
            float dz = rz - skp[k * 3 + 2];
            float sq2 = dx * dx + dy * dy + dz * dz;
            float dist = sqrtf(fmaxf(sq2, 1e-12f));
            float wt = fmaxf(0.0f, 1.0f - dist / 0.2f);
            sw2[wid][L][k] = make_float2(wt, wt);
        }
    }
    __syncwarp();

    const float* fb = feat1 + (size_t)b * N1 * C1;
    unsigned long long fxy[NSAMP], fzw[NSAMP];
    #pragma unroll
    for (int s = 0; s < NSAMP; ++s) {
        const int is = __shfl_sync(0xffffffffu, sid, s);
        const float4 v = *(const float4*)(fb + (size_t)is * C1 + 4 * L);
        PACKF2(fxy[s], v.x, v.y);
        PACKF2(fzw[s], v.z, v.w);
    }

    unsigned long long a0[KP], a1[KP];
    #pragma unroll
    for (int k = 0; k < KP; ++k) { a0[k] = 0ull; a1[k] = 0ull; }

    #pragma unroll
    for (int s = 0; s < NSAMP; ++s) {
        #pragma unroll
        for (int k = 0; k < KP; ++k) {
            const unsigned long long wp =
                *(const unsigned long long*)&sw2[wid][s][k];
            FFMA2(a0[k], wp, fxy[s]);
            FFMA2(a1[k], wp, fzw[s]);
        }
    }

    const size_t qbase = (size_t)q * KDIM + 4 * L;
    #pragma unroll
    for (int k = 0; k < KP; ++k) {
        float vx, vy, vz, vw;
        UNPACKF2(vx, vy, a0[k]);
        UNPACKF2(vz, vw, a1[k]);
        __half2 h0 = __floats2half2_rn(vx, vy);
        __half2 h1 = __floats2half2_rn(vz, vw);
        uint2 st;
        st.x = *(const uint32_t*)&h0;
        st.y = *(const uint32_t*)&h1;
        *(uint2*)(g_a + qbase + k * C1) = st;
    }
}

// ---------------------------------------------------------------------------
// Kernel 3: mma.sync pure fp16 GEMM (1 product), fused concat.
// M=32768 (256 CTAs of 128 rows), N=128, K=1920 in 60 chunks of 32 (64B rows).
// 8 warps in 2(M)x4(N): warp tile 64x32. 4-stage cp.async (16KB/stage),
// 64KB smem -> 2 CTAs/SM, 1 full wave on 148 SMs.
// ---------------------------------------------------------------------------
#define A_SUB       8192                // 128 rows x 64B
#define B_SUB       8192                // 128 rows x 64B
#define STAGE_BYTES (A_SUB + B_SUB)           // 16KB
#define NSTAGE      4
#define GEMM_SMEM   (NSTAGE * STAGE_BYTES)    // 64KB

__global__ __launch_bounds__(256, 2)
void gemm_kernel(const float* __restrict__ feat2, float* __restrict__ out)
{
    extern __shared__ __align__(1024) char dsmem[];

    const int tid = threadIdx.x;
    const int wid = tid >> 5;
    const int L   = tid & 31;
    const int m0  = blockIdx.x * 128;
    const int wm  = wid & 1;              // 0..1 (M, 64 rows each)
    const int wn  = wid >> 1;             // 0..3 (N, 32 cols each)

    const uint32_t base = smem_u32(dsmem);

    const char* srcA = (const char*)g_a + (size_t)m0 * (KDIM * 2);
    const char* srcB = (const char*)g_b;

    // one stage: A 128 rows x 4 quads (512 ops), B 128 rows x 4 quads (512)
    auto load_stage = [&](int chunk, int buf) {
        const uint32_t sbase = base + buf * STAGE_BYTES;
        #pragma unroll
        for (int v = 0; v < 2; ++v) {
            int idx = v * 256 + tid;          // 0..511
            int row = idx >> 2;               // 0..127
            int kb  = (idx & 3) << 4;         // 0..48
            const char* g = srcA + (size_t)row * (KDIM * 2) + chunk * 64 + kb;
            uint32_t sa = sbase + sw64(row, kb);
            asm volatile("cp.async.cg.shared.global [%0], [%1], 16;"
                         :: "r"(sa), "l"(g));
        }
        #pragma unroll
        for (int v = 0; v < 2; ++v) {
            int idx = v * 256 + tid;          // 0..511
            int row = idx >> 2;               // 0..127
            int kb  = (idx & 3) << 4;
            const char* g = srcB + (size_t)row * (KDIM * 2) + chunk * 64 + kb;
            uint32_t sa = sbase + A_SUB + sw64(row, kb);
            asm volatile("cp.async.cg.shared.global [%0], [%1], 16;"
                         :: "r"(sa), "l"(g));
        }
        asm volatile("cp.async.commit_group;" ::: "memory");
    };

    // ldmatrix per-thread offsets (64B rows, quad swizzle)
    int aRow = wm * 64 + (L & 15);                  // + mt*16
    int aKb  = (L >> 4) * 16;                       // 0 or 16
    int bRow = wn * 32 + ((L >> 4) << 3) + (L & 7); // + ng*16
    int bKb  = ((L >> 3) & 1) * 16;

    uint32_t aOff[4], aXor[4];
    #pragma unroll
    for (int mt = 0; mt < 4; ++mt) {
        int r = aRow + mt * 16;
        aOff[mt] = r * 64;
        aXor[mt] = ((r >> 1) & 3) << 4;
    }
    uint32_t bOff[2], bXor[2];
    #pragma unroll
    for (int ng = 0; ng < 2; ++ng) {
        int r = bRow + ng * 16;
        bOff[ng] = r * 64;
        bXor[ng] = ((r >> 1) & 3) << 4;
    }

    float acc[4][4][4];
    #pragma unroll
    for (int i = 0; i < 4; ++i)
        #pragma unroll
        for (int j = 0; j < 4; ++j)
            #pragma unroll
            for (int k = 0; k < 4; ++k) acc[i][j][k] = 0.0f;

    load_stage(0, 0);
    load_stage(1, 1);
    load_stage(2, 2);

    // fused concat: copy feat2 rows [m0, m0+128) into out[:,128:192)
    {
        const float* f2 = feat2 + (size_t)m0 * C2;
        float* o2 = out + (size_t)m0 * OUTC + FOUT;
        #pragma unroll
        for (int i = 0; i < 8; ++i) {
            int v = i * 256 + tid;            // 0..2047
            int row = v >> 4;
            int j   = v & 15;
            float4 t = *(const float4*)(f2 + (size_t)row * C2 + j * 4);
            *(float4*)(o2 + (size_t)row * OUTC + j * 4) = t;
        }
    }

    for (int i = 0; i < NCHUNK; ++i) {
        const int buf = i & 3;
        if (i + 2 < NCHUNK)
            asm volatile("cp.async.wait_group 2;" ::: "memory");
        else if (i + 1 < NCHUNK)
            asm volatile("cp.async.wait_group 1;" ::: "memory");
        else
            asm volatile("cp.async.wait_group 0;" ::: "memory");
        __syncthreads();

        const uint32_t sb = base + buf * STAGE_BYTES;
        const uint32_t sA = sb;
        const uint32_t sB = sb + A_SUB;

        #pragma unroll
        for (int ks = 0; ks < 2; ++ks) {
            const uint32_t kA = ks * 32 + aKb;
            const uint32_t kB = ks * 32 + bKb;
            uint32_t a[4][4];
            #pragma unroll
            for (int mt = 0; mt < 4; ++mt)
                ldsm4(a[mt], sA + aOff[mt] + (kA ^ aXor[mt]));
            #pragma unroll
            for (int ng = 0; ng < 2; ++ng) {
                uint32_t bb[4];
                ldsm4(bb, sB + bOff[ng] + (kB ^ bXor[ng]));
                #pragma unroll
                for (int mt = 0; mt < 4; ++mt) {
                    mma16816h(acc[mt][ng * 2 + 0], a[mt], &bb[0]);
                    mma16816h(acc[mt][ng * 2 + 1], a[mt], &bb[2]);
                }
            }
        }

        if (i + 3 < NCHUNK) load_stage(i + 3, (i + 3) & 3);
    }

    #pragma unroll
    for (int mt = 0; mt < 4; ++mt) {
        #pragma unroll
        for (int nt = 0; nt < 4; ++nt) {
            const float* c = acc[mt][nt];
            int row = m0 + wm * 64 + mt * 16 + (L >> 2);
            int col = wn * 32 + nt * 8 + (L & 3) * 2;
            float2 v0, v1;
            v0.x = fmaxf(c[0], 0.0f); v0.y = fmaxf(c[1], 0.0f);
            v1.x = fmaxf(c[2], 0.0f); v1.y = fmaxf(c[3], 0.0f);
            *(float2*)(out + (size_t)row * OUTC + col)       = v0;
            *(float2*)(out + (size_t)(row + 8) * OUTC + col) = v1;
        }
    }
}

// ---------------------------------------------------------------------------
// Launch
// ---------------------------------------------------------------------------
extern "C" void kernel_launch(void* const* d_in, const int* in_sizes, int n_in,
                              void* d_out, int out_size)
{
    const float* xyz1  = (const float*)d_in[0];
    const float* feat1 = (const float*)d_in[1];
    const float* xyz2  = (const float*)d_in[2];
    const float* feat2 = (const float*)d_in[3];
    const float* kp    = (const float*)d_in[4];
    const float* W     = (const float*)d_in[5];
    float* out = (float*)d_out;

    cudaFuncSetAttribute(gemm_kernel,
                         cudaFuncAttributeMaxDynamicSharedMemorySize, GEMM_SMEM);

    prep_kernel<<<2 * BATCH + (KDIM * FOUT) / 512, 512>>>(xyz1, xyz2, W);
    knn_kernel<<<dim3(N2 / 256, BATCH), 256>>>(xyz2);
    wf_kernel<<<NQ / 4, 128>>>(xyz1, feat1, xyz2, kp);
    gemm_kernel<<<NQ / 128, 256, GEMM_SMEM>>>(feat2, out);
}

// round 16
// speedup vs baseline: 1.7675x; 1.0634x over previous
#include <cuda_runtime.h>
#include <cuda_fp16.h>
#include <cstdint>

// ---------------------------------------------------------------------------
// Problem constants
// ---------------------------------------------------------------------------
#define BATCH   4
#define N1      2048
#define N2      8192
#define C1      128
#define C2      64
#define KP      15
#define FOUT    128
#define NSAMP   16
#define NQ      (BATCH * N2)          // 32768 queries
#define KDIM    (KP * C1)             // 1920
#define OUTC    (FOUT + C2)           // 192
#define NCHUNK  (KDIM / 32)           // 60 K-chunks of 32 fp16 (64B rows)

#define GRID    8                     // 8x8x8 spatial bins
#define NCELL   (GRID * GRID * GRID)  // 512
#define CELLH   0.125f

// Scratch (device globals)
__device__ int     g_idx[NQ * NSAMP];
__device__ float4  g_sxyz[BATCH * N1];        // binned points (x,y,z,idx)
__device__ int     g_cellstart[BATCH * (NCELL + 1)];
__device__ int     g_qorder[NQ];              // queries in cell-sorted order
__device__ __half  g_a[(size_t)NQ * KDIM];    // wf in fp16, row-major (q, kc)
__device__ __half  g_b[(size_t)FOUT * KDIM];  // W^T in fp16, (f, kc)

// ---------------------------------------------------------------------------
// Helpers
// ---------------------------------------------------------------------------
__device__ __forceinline__ uint32_t smem_u32(const void* p) {
    uint32_t a;
    asm("{ .reg .u64 t; cvta.to.shared.u64 t, %1; cvt.u32.u64 %0, t; }"
        : "=r"(a) : "l"(p));
    return a;
}
__device__ __forceinline__ void ldsm4(uint32_t* r, uint32_t addr) {
    asm volatile("ldmatrix.sync.aligned.m8n8.x4.shared.b16 {%0,%1,%2,%3}, [%4];"
                 : "=r"(r[0]), "=r"(r[1]), "=r"(r[2]), "=r"(r[3]) : "r"(addr));
}
__device__ __forceinline__ void ldsm2t(uint32_t& b0, uint32_t& b1, uint32_t addr) {
    asm volatile("ldmatrix.sync.aligned.m8n8.x2.trans.shared.b16 {%0,%1}, [%2];"
                 : "=r"(b0), "=r"(b1) : "r"(addr));
}
__device__ __forceinline__ void mma16816h(float* c, const uint32_t* a,
                                          const uint32_t* b) {
    asm volatile(
        "mma.sync.aligned.m16n8k16.row.col.f32.f16.f16.f32 "
        "{%0,%1,%2,%3}, {%4,%5,%6,%7}, {%8,%9}, {%0,%1,%2,%3};"
        : "+f"(c[0]), "+f"(c[1]), "+f"(c[2]), "+f"(c[3])
        : "r"(a[0]), "r"(a[1]), "r"(a[2]), "r"(a[3]), "r"(b[0]), "r"(b[1]));
}
__device__ __forceinline__ int cellof(float x) {
    int c = (int)(x * (float)GRID);
    return min(GRID - 1, max(0, c));
}

// 64B-row smem swizzle for gemm tiles
__device__ __forceinline__ uint32_t sw64(int row, int kb) {
    return row * 64 + (kb ^ (((row >> 1) & 3) << 4));
}

// ---------------------------------------------------------------------------
// Kernel 0: prep.
//   blocks [0, BATCH):          bin xyz1 points into cells
//   blocks [BATCH, 2*BATCH):    bin xyz2 queries (cell-sorted order only)
//   blocks [2*BATCH, ...):      W fp16 transpose
// ---------------------------------------------------------------------------
__global__ __launch_bounds__(512) void prep_kernel(
    const float* __restrict__ xyz1, const float* __restrict__ xyz2,
    const float* __restrict__ W)
{
    const int t = threadIdx.x;

    if (blockIdx.x >= 2 * BATCH) {
        const int i = (blockIdx.x - 2 * BATCH) * 512 + t;
        const int kc = i / FOUT;
        const int f  = i % FOUT;
        g_b[(size_t)f * KDIM + kc] = __float2half_rn(W[i]);
        return;
    }

    __shared__ int cnt[NCELL];
    __shared__ int sscan[NCELL];
    __shared__ int cursor[NCELL];

    cnt[t] = 0;
    __syncthreads();

    if (blockIdx.x < BATCH) {
        const int b = blockIdx.x;
        float px[N1 / 512], py[N1 / 512], pz[N1 / 512];
        int   cl[N1 / 512];
        #pragma unroll
        for (int k = 0; k < N1 / 512; ++k) {
            const int i = t + k * 512;
            px[k] = xyz1[((size_t)b * N1 + i) * 3 + 0];
            py[k] = xyz1[((size_t)b * N1 + i) * 3 + 1];
            pz[k] = xyz1[((size_t)b * N1 + i) * 3 + 2];
            cl[k] = (cellof(pz[k]) << 6) | (cellof(py[k]) << 3) | cellof(px[k]);
            atomicAdd(&cnt[cl[k]], 1);
        }
        __syncthreads();

        sscan[t] = cnt[t];
        __syncthreads();
        #pragma unroll
        for (int off = 1; off < NCELL; off <<= 1) {
            int add = (t >= off) ? sscan[t - off] : 0;
            __syncthreads();
            sscan[t] += add;
            __syncthreads();
        }
        const int excl = sscan[t] - cnt[t];
        g_cellstart[b * (NCELL + 1) + t] = excl;
        if (t == NCELL - 1) g_cellstart[b * (NCELL + 1) + NCELL] = N1;
        cursor[t] = excl;
        __syncthreads();

        #pragma unroll
        for (int k = 0; k < N1 / 512; ++k) {
            const int i = t + k * 512;
            const int pos = atomicAdd(&cursor[cl[k]], 1);
            g_sxyz[b * N1 + pos] =
                make_float4(px[k], py[k], pz[k], __int_as_float(i));
        }
    } else {
        const int b = blockIdx.x - BATCH;
        int cl[N2 / 512];
        #pragma unroll
        for (int k = 0; k < N2 / 512; ++k) {
            const int i = t + k * 512;
            const float x = xyz2[((size_t)b * N2 + i) * 3 + 0];
            const float y = xyz2[((size_t)b * N2 + i) * 3 + 1];
            const float z = xyz2[((size_t)b * N2 + i) * 3 + 2];
            cl[k] = (cellof(z) << 6) | (cellof(y) << 3) | cellof(x);
            atomicAdd(&cnt[cl[k]], 1);
        }
        __syncthreads();

        sscan[t] = cnt[t];
        __syncthreads();
        #pragma unroll
        for (int off = 1; off < NCELL; off <<= 1) {
            int add = (t >= off) ? sscan[t - off] : 0;
            __syncthreads();
            sscan[t] += add;
            __syncthreads();
        }
        cursor[t] = sscan[t] - cnt[t];
        __syncthreads();

        #pragma unroll
        for (int k = 0; k < N2 / 512; ++k) {
            const int i = t + k * 512;
            const int pos = atomicAdd(&cursor[cl[k]], 1);
            g_qorder[b * N2 + pos] = i;
        }
    }
}

// ---------------------------------------------------------------------------
// Kernel 1: kNN via expanding Chebyshev shells, contiguous row-run scans.
// Cell-sorted query order; output to the original query slot. (Frozen.)
// ---------------------------------------------------------------------------
__global__ __launch_bounds__(256) void knn_kernel(const float* __restrict__ xyz2)
{
    __shared__ float4 spt[N1];            // 32KB
    __shared__ int    cst[NCELL + 1];

    const int b = blockIdx.y;
    for (int i = threadIdx.x; i < N1; i += 256)
        spt[i] = g_sxyz[b * N1 + i];
    for (int i = threadIdx.x; i < NCELL + 1; i += 256)
        cst[i] = g_cellstart[b * (NCELL + 1) + i];
    __syncthreads();

    const int qq = g_qorder[b * N2 + blockIdx.x * 256 + threadIdx.x];
    const size_t qg = (size_t)b * N2 + qq;
    const float qx = xyz2[qg * 3 + 0];
    const float qy = xyz2[qg * 3 + 1];
    const float qz = xyz2[qg * 3 + 2];
    const int cx = cellof(qx), cy = cellof(qy), cz = cellof(qz);

    float dk[NSAMP];
    int   ik[NSAMP];
    #pragma unroll
    for (int p = 0; p < NSAMP; ++p) { dk[p] = 3.4e38f; ik[p] = 0; }

    auto scan_run = [&](int rowbase, int xa, int xb) {
        const int pe = cst[rowbase + xb + 1];
        for (int p = cst[rowbase + xa]; p < pe; ++p) {
            const float4 P = spt[p];
            const float dx = qx - P.x;
            const float dy = qy - P.y;
            const float dz = qz - P.z;
            const float d2 = fmaf(dx, dx, fmaf(dy, dy, dz * dz));
            if (d2 < dk[NSAMP - 1]) {
                dk[NSAMP - 1] = d2;
                ik[NSAMP - 1] = __float_as_int(P.w);
                #pragma unroll
                for (int s = NSAMP - 1; s > 0; --s) {
                    if (dk[s] < dk[s - 1]) {
                        float td = dk[s]; dk[s] = dk[s-1]; dk[s-1] = td;
                        int   ti = ik[s]; ik[s] = ik[s-1]; ik[s-1] = ti;
                    }
                }
            }
        }
    };

    for (int R = 0; R < GRID; ++R) {
        const int zlo = max(cz - R, 0), zhi = min(cz + R, GRID - 1);
        const int ylo = max(cy - R, 0), yhi = min(cy + R, GRID - 1);
        const int xlo = max(cx - R, 0), xhi = min(cx + R, GRID - 1);
        for (int z = zlo; z <= zhi; ++z) {
            const int az = abs(z - cz);
            for (int y = ylo; y <= yhi; ++y) {
                const int ay = abs(y - cy);
                const int rowbase = (z << 6) | (y << 3);
                if (az == R || ay == R) {
                    scan_run(rowbase, xlo, xhi);       // full row in shell
                } else {
                    if (cx - R >= 0)        scan_run(rowbase, cx - R, cx - R);
                    if (cx + R <= GRID - 1) scan_run(rowbase, cx + R, cx + R);
                }
            }
        }
        const float bnd = (float)R * CELLH;
        if (dk[NSAMP - 1] < bnd * bnd) break;
    }

    int* o = g_idx + qg * NSAMP;
    #pragma unroll
    for (int p = 0; p < NSAMP; ++p) o[p] = ik[p];
}

// ---------------------------------------------------------------------------
// Kernel 2: weighted aggregation on TENSOR CORES.
// One warp per query: D[15x128] = W[15x16] x F[16x128] via 16 mma.m16n8k16.
// A (weights) built directly in registers per the m16n8k16 A-frag layout;
// F staged to swizzled smem as fp16, fetched with ldmatrix.x2.trans.
// ---------------------------------------------------------------------------
__global__ __launch_bounds__(128) void wf_kernel(
    const float* __restrict__ xyz1, const float* __restrict__ feat1,
    const float* __restrict__ xyz2, const float* __restrict__ kp)
{
    const int wid = threadIdx.x >> 5;
    const int L   = threadIdx.x & 31;
    const int qi  = blockIdx.x * 4 + wid;    // sorted index
    const int b   = qi >> 13;

    __shared__ float skp[48];                         // KP*3 = 45, pad to 48
    __shared__ float srel[4][NSAMP][4];               // [warp][s][xyz,pad]
    __shared__ int   sq[4];
    __shared__ __align__(256) __half sF[4][NSAMP][C1];  // 4KB per warp

    if (threadIdx.x < 48)
        skp[threadIdx.x] = (threadIdx.x < KP * 3) ? kp[threadIdx.x] : 0.0f;
    if (L == 0) sq[wid] = b * N2 + g_qorder[qi];
    __syncthreads();

    const int q = sq[wid];                    // original query id (global)

    int sid = 0;
    if (L < NSAMP) {
        sid = g_idx[(size_t)q * NSAMP + L];
        srel[wid][L][0] = xyz1[((size_t)b * N1 + sid) * 3 + 0] - xyz2[(size_t)q * 3 + 0];
        srel[wid][L][1] = xyz1[((size_t)b * N1 + sid) * 3 + 1] - xyz2[(size_t)q * 3 + 1];
        srel[wid][L][2] = xyz1[((size_t)b * N1 + sid) * 3 + 2] - xyz2[(size_t)q * 3 + 2];
    }
    __syncwarp();

    // stage features: lane L handles cols [4L, 4L+4) of every neighbor row s.
    // swizzle: quad index (byte>>4) XOR row (full 4-bit) -> conflict-free
    // for both the STS here and the 16-row ldmatrix below.
    const float* fb = feat1 + (size_t)b * N1 * C1;
    char* fB = (char*)&sF[wid][0][0];
    #pragma unroll
    for (int s = 0; s < NSAMP; ++s) {
        const int is = __shfl_sync(0xffffffffu, sid, s);
        const float4 v = *(const float4*)(fb + (size_t)is * C1 + 4 * L);
        __half2 h0 = __floats2half2_rn(v.x, v.y);
        __half2 h1 = __floats2half2_rn(v.z, v.w);
        const int off  = 8 * L;                 // byte offset in 256B row
        const int swq  = (off >> 4) ^ s;        // quad ^ row
        uint2 st;
        st.x = *(const uint32_t*)&h0;
        st.y = *(const uint32_t*)&h1;
        *(uint2*)(fB + s * 256 + (swq << 4) + (off & 15)) = st;
    }

    // build A fragments (weights) in registers
    const int r  = L >> 2;                    // 0..7
    const int c0 = (L & 3) * 2;               // s base 0,2,4,6
    float relv[4][3];
    #pragma unroll
    for (int j = 0; j < 4; ++j) {
        const int s = c0 + (j & 1) + (j >> 1) * 8;   // c0, c0+1, c0+8, c0+9
        relv[j][0] = srel[wid][s][0];
        relv[j][1] = srel[wid][s][1];
        relv[j][2] = srel[wid][s][2];
    }
    uint32_t afr[4];
    #pragma unroll
    for (int h = 0; h < 2; ++h) {
        const int k = r + 8 * h;              // 0..15 (15 = pad row)
        const float kx = skp[k * 3 + 0];
        const float ky = skp[k * 3 + 1];
        const float kz = skp[k * 3 + 2];
        float w[4];
        #pragma unroll
        for (int j = 0; j < 4; ++j) {
            const float dx = relv[j][0] - kx;
            const float dy = relv[j][1] - ky;
            const float dz = relv[j][2] - kz;
            const float sq2 = dx * dx + dy * dy + dz * dz;
            const float dist = sqrtf(fmaxf(sq2, 1e-12f));
            w[j] = (k == KP) ? 0.0f : fmaxf(0.0f, 1.0f - dist / 0.2f);
        }
        __half2 lo = __floats2half2_rn(w[0], w[1]);   // (k, s=c0), (k, c0+1)
        __half2 hi = __floats2half2_rn(w[2], w[3]);   // (k, c0+8), (k, c0+9)
        afr[h]     = *(const uint32_t*)&lo;           // a0 (h=0: row r), a1 (row r+8)
        afr[2 + h] = *(const uint32_t*)&hi;           // a2, a3 (k+8 halves)
    }
    __syncwarp();   // sF fully written by this warp

    // 16 mma chunks of 8 output channels
    const uint32_t fbase = smem_u32(&sF[wid][0][0]);
    const int rr = L & 15;                    // ldmatrix row provider
    __half* ga = g_a + (size_t)q * KDIM;
    #pragma unroll
    for (int chunk = 0; chunk < 16; ++chunk) {
        uint32_t b0, b1;
        ldsm2t(b0, b1, fbase + rr * 256 + (((chunk ^ rr) & 15) << 4));
        uint32_t bfr[2] = { b0, b1 };
        float d[4] = { 0.0f, 0.0f, 0.0f, 0.0f };
        mma16816h(d, afr, bfr);
        const int nc = chunk * 8 + c0;
        __half2 o0 = __floats2half2_rn(d[0], d[1]);
        *(__half2*)(ga + r * C1 + nc) = o0;
        if (r < 7) {                          // k = r+8 (skip pad row 15)
            __half2 o1 = __floats2half2_rn(d[2], d[3]);
            *(__half2*)(ga + (r + 8) * C1 + nc) = o1;
        }
    }
}

// ---------------------------------------------------------------------------
// Kernel 3: mma.sync pure fp16 GEMM (1 product), fused concat. (Frozen R15.)
// ---------------------------------------------------------------------------
#define A_SUB       8192                // 128 rows x 64B
#define B_SUB       8192                // 128 rows x 64B
#define STAGE_BYTES (A_SUB + B_SUB)           // 16KB
#define NSTAGE      4
#define GEMM_SMEM   (NSTAGE * STAGE_BYTES)    // 64KB

__global__ __launch_bounds__(256, 2)
void gemm_kernel(const float* __restrict__ feat2, float* __restrict__ out)
{
    extern __shared__ __align__(1024) char dsmem[];

    const int tid = threadIdx.x;
    const int wid = tid >> 5;
    const int L   = tid & 31;
    const int m0  = blockIdx.x * 128;
    const int wm  = wid & 1;              // 0..1 (M, 64 rows each)
    const int wn  = wid >> 1;             // 0..3 (N, 32 cols each)

    const uint32_t base = smem_u32(dsmem);

    const char* srcA = (const char*)g_a + (size_t)m0 * (KDIM * 2);
    const char* srcB = (const char*)g_b;

    auto load_stage = [&](int chunk, int buf) {
        const uint32_t sbase = base + buf * STAGE_BYTES;
        #pragma unroll
        for (int v = 0; v < 2; ++v) {
            int idx = v * 256 + tid;          // 0..511
            int row = idx >> 2;               // 0..127
            int kb  = (idx & 3) << 4;         // 0..48
            const char* g = srcA + (size_t)row * (KDIM * 2) + chunk * 64 + kb;
            uint32_t sa = sbase + sw64(row, kb);
            asm volatile("cp.async.cg.shared.global [%0], [%1], 16;"
                         :: "r"(sa), "l"(g));
        }
        #pragma unroll
        for (int v = 0; v < 2; ++v) {
            int idx = v * 256 + tid;          // 0..511
            int row = idx >> 2;               // 0..127
            int kb  = (idx & 3) << 4;
            const char* g = srcB + (size_t)row * (KDIM * 2) + chunk * 64 + kb;
            uint32_t sa = sbase + A_SUB + sw64(row, kb);
            asm volatile("cp.async.cg.shared.global [%0], [%1], 16;"
                         :: "r"(sa), "l"(g));
        }
        asm volatile("cp.async.commit_group;" ::: "memory");
    };

    int aRow = wm * 64 + (L & 15);                  // + mt*16
    int aKb  = (L >> 4) * 16;                       // 0 or 16
    int bRow = wn * 32 + ((L >> 4) << 3) + (L & 7); // + ng*16
    int bKb  = ((L >> 3) & 1) * 16;

    uint32_t aOff[4], aXor[4];
    #pragma unroll
    for (int mt = 0; mt < 4; ++mt) {
        int r = aRow + mt * 16;
        aOff[mt] = r * 64;
        aXor[mt] = ((r >> 1) & 3) << 4;
    }
    uint32_t bOff[2], bXor[2];
    #pragma unroll
    for (int ng = 0; ng < 2; ++ng) {
        int r = bRow + ng * 16;
        bOff[ng] = r * 64;
        bXor[ng] = ((r >> 1) & 3) << 4;
    }

    float acc[4][4][4];
    #pragma unroll
    for (int i = 0; i < 4; ++i)
        #pragma unroll
        for (int j = 0; j < 4; ++j)
            #pragma unroll
            for (int k = 0; k < 4; ++k) acc[i][j][k] = 0.0f;

    load_stage(0, 0);
    load_stage(1, 1);
    load_stage(2, 2);

    // fused concat: copy feat2 rows [m0, m0+128) into out[:,128:192)
    {
        const float* f2 = feat2 + (size_t)m0 * C2;
        float* o2 = out + (size_t)m0 * OUTC + FOUT;
        #pragma unroll
        for (int i = 0; i < 8; ++i) {
            int v = i * 256 + tid;            // 0..2047
            int row = v >> 4;
            int j   = v & 15;
            float4 t = *(const float4*)(f2 + (size_t)row * C2 + j * 4);
            *(float4*)(o2 + (size_t)row * OUTC + j * 4) = t;
        }
    }

    for (int i = 0; i < NCHUNK; ++i) {
        const int buf = i & 3;
        if (i + 2 < NCHUNK)
            asm volatile("cp.async.wait_group 2;" ::: "memory");
        else if (i + 1 < NCHUNK)
            asm volatile("cp.async.wait_group 1;" ::: "memory");
        else
            asm volatile("cp.async.wait_group 0;" ::: "memory");
        __syncthreads();

        const uint32_t sb = base + buf * STAGE_BYTES;
        const uint32_t sA = sb;
        const uint32_t sB = sb + A_SUB;

        #pragma unroll
        for (int ks = 0; ks < 2; ++ks) {
            const uint32_t kA = ks * 32 + aKb;
            const uint32_t kB = ks * 32 + bKb;
            uint32_t a[4][4];
            #pragma unroll
            for (int mt = 0; mt < 4; ++mt)
                ldsm4(a[mt], sA + aOff[mt] + (kA ^ aXor[mt]));
            #pragma unroll
            for (int ng = 0; ng < 2; ++ng) {
                uint32_t bb[4];
                ldsm4(bb, sB + bOff[ng] + (kB ^ bXor[ng]));
                #pragma unroll
                for (int mt = 0; mt < 4; ++mt) {
                    mma16816h(acc[mt][ng * 2 + 0], a[mt], &bb[0]);
                    mma16816h(acc[mt][ng * 2 + 1], a[mt], &bb[2]);
                }
            }
        }

        if (i + 3 < NCHUNK) load_stage(i + 3, (i + 3) & 3);
    }

    #pragma unroll
    for (int mt = 0; mt < 4; ++mt) {
        #pragma unroll
        for (int nt = 0; nt < 4; ++nt) {
            const float* c = acc[mt][nt];
            int row = m0 + wm * 64 + mt * 16 + (L >> 2);
            int col = wn * 32 + nt * 8 + (L & 3) * 2;
            float2 v0, v1;
            v0.x = fmaxf(c[0], 0.0f); v0.y = fmaxf(c[1], 0.0f);
            v1.x = fmaxf(c[2], 0.0f); v1.y = fmaxf(c[3], 0.0f);
            *(float2*)(out + (size_t)row * OUTC + col)       = v0;
            *(float2*)(out + (size_t)(row + 8) * OUTC + col) = v1;
        }
    }
}

// ---------------------------------------------------------------------------
// Launch
// ---------------------------------------------------------------------------
extern "C" void kernel_launch(void* const* d_in, const int* in_sizes, int n_in,
                              void* d_out, int out_size)
{
    const float* xyz1  = (const float*)d_in[0];
    const float* feat1 = (const float*)d_in[1];
    const float* xyz2  = (const float*)d_in[2];
    const float* feat2 = (const float*)d_in[3];
    const float* kp    = (const float*)d_in[4];
    const float* W     = (const float*)d_in[5];
    float* out = (float*)d_out;

    cudaFuncSetAttribute(gemm_kernel,
                         cudaFuncAttributeMaxDynamicSharedMemorySize, GEMM_SMEM);

    prep_kernel<<<2 * BATCH + (KDIM * FOUT) / 512, 512>>>(xyz1, xyz2, W);
    knn_kernel<<<dim3(N2 / 256, BATCH), 256>>>(xyz2);
    wf_kernel<<<NQ / 4, 128>>>(xyz1, feat1, xyz2, kp);
    gemm_kernel<<<NQ / 128, 256, GEMM_SMEM>>>(feat2, out);
}

// round 17
// speedup vs baseline: 1.8558x; 1.0499x over previous
#include <cuda_runtime.h>
#include <cuda_fp16.h>
#include <cstdint>

// ---------------------------------------------------------------------------
// Problem constants
// ---------------------------------------------------------------------------
#define BATCH   4
#define N1      2048
#define N2      8192
#define C1      128
#define C2      64
#define KP      15
#define FOUT    128
#define NSAMP   16
#define NQ      (BATCH * N2)          // 32768 queries
#define KDIM    (KP * C1)             // 1920
#define OUTC    (FOUT + C2)           // 192
#define NCHUNK  (KDIM / 32)           // 60 K-chunks of 32 fp16 (64B rows)

#define GRID    8                     // 8x8x8 spatial bins
#define NCELL   (GRID * GRID * GRID)  // 512
#define CELLH   0.125f

// Scratch (device globals)
__device__ int     g_idx[NQ * NSAMP];
__device__ float4  g_sxyz[BATCH * N1];        // binned points (x,y,z,idx)
__device__ int     g_cellstart[BATCH * (NCELL + 1)];
__device__ int     g_qorder[NQ];              // queries in cell-sorted order
__device__ __half  g_a[(size_t)NQ * KDIM];    // wf in fp16, row-major (q, kc)
__device__ __half  g_b[(size_t)FOUT * KDIM];  // W^T in fp16, (f, kc)

// ---------------------------------------------------------------------------
// Helpers
// ---------------------------------------------------------------------------
__device__ __forceinline__ uint32_t smem_u32(const void* p) {
    uint32_t a;
    asm("{ .reg .u64 t; cvta.to.shared.u64 t, %1; cvt.u32.u64 %0, t; }"
        : "=r"(a) : "l"(p));
    return a;
}
__device__ __forceinline__ void ldsm4(uint32_t* r, uint32_t addr) {
    asm volatile("ldmatrix.sync.aligned.m8n8.x4.shared.b16 {%0,%1,%2,%3}, [%4];"
                 : "=r"(r[0]), "=r"(r[1]), "=r"(r[2]), "=r"(r[3]) : "r"(addr));
}
__device__ __forceinline__ void ldsm2t(uint32_t& b0, uint32_t& b1, uint32_t addr) {
    asm volatile("ldmatrix.sync.aligned.m8n8.x2.trans.shared.b16 {%0,%1}, [%2];"
                 : "=r"(b0), "=r"(b1) : "r"(addr));
}
__device__ __forceinline__ void mma16816h(float* c, const uint32_t* a,
                                          const uint32_t* b) {
    asm volatile(
        "mma.sync.aligned.m16n8k16.row.col.f32.f16.f16.f32 "
        "{%0,%1,%2,%3}, {%4,%5,%6,%7}, {%8,%9}, {%0,%1,%2,%3};"
        : "+f"(c[0]), "+f"(c[1]), "+f"(c[2]), "+f"(c[3])
        : "r"(a[0]), "r"(a[1]), "r"(a[2]), "r"(a[3]), "r"(b[0]), "r"(b[1]));
}
__device__ __forceinline__ int cellof(float x) {
    int c = (int)(x * (float)GRID);
    return min(GRID - 1, max(0, c));
}

// 64B-row smem swizzle for gemm tiles
__device__ __forceinline__ uint32_t sw64(int row, int kb) {
    return row * 64 + (kb ^ (((row >> 1) & 3) << 4));
}

// ---------------------------------------------------------------------------
// Kernel 0: prep.
//   blocks [0, BATCH):          bin xyz1 points into cells
//   blocks [BATCH, 2*BATCH):    bin xyz2 queries (cell-sorted order only)
//   blocks [2*BATCH, ...):      W fp16 transpose
// ---------------------------------------------------------------------------
__global__ __launch_bounds__(512) void prep_kernel(
    const float* __restrict__ xyz1, const float* __restrict__ xyz2,
    const float* __restrict__ W)
{
    const int t = threadIdx.x;

    if (blockIdx.x >= 2 * BATCH) {
        const int i = (blockIdx.x - 2 * BATCH) * 512 + t;
        const int kc = i / FOUT;
        const int f  = i % FOUT;
        g_b[(size_t)f * KDIM + kc] = __float2half_rn(W[i]);
        return;
    }

    __shared__ int cnt[NCELL];
    __shared__ int sscan[NCELL];
    __shared__ int cursor[NCELL];

    cnt[t] = 0;
    __syncthreads();

    if (blockIdx.x < BATCH) {
        const int b = blockIdx.x;
        float px[N1 / 512], py[N1 / 512], pz[N1 / 512];
        int   cl[N1 / 512];
        #pragma unroll
        for (int k = 0; k < N1 / 512; ++k) {
            const int i = t + k * 512;
            px[k] = xyz1[((size_t)b * N1 + i) * 3 + 0];
            py[k] = xyz1[((size_t)b * N1 + i) * 3 + 1];
            pz[k] = xyz1[((size_t)b * N1 + i) * 3 + 2];
            cl[k] = (cellof(pz[k]) << 6) | (cellof(py[k]) << 3) | cellof(px[k]);
            atomicAdd(&cnt[cl[k]], 1);
        }
        __syncthreads();

        sscan[t] = cnt[t];
        __syncthreads();
        #pragma unroll
        for (int off = 1; off < NCELL; off <<= 1) {
            int add = (t >= off) ? sscan[t - off] : 0;
            __syncthreads();
            sscan[t] += add;
            __syncthreads();
        }
        const int excl = sscan[t] - cnt[t];
        g_cellstart[b * (NCELL + 1) + t] = excl;
        if (t == NCELL - 1) g_cellstart[b * (NCELL + 1) + NCELL] = N1;
        cursor[t] = excl;
        __syncthreads();

        #pragma unroll
        for (int k = 0; k < N1 / 512; ++k) {
            const int i = t + k * 512;
            const int pos = atomicAdd(&cursor[cl[k]], 1);
            g_sxyz[b * N1 + pos] =
                make_float4(px[k], py[k], pz[k], __int_as_float(i));
        }
    } else {
        const int b = blockIdx.x - BATCH;
        int cl[N2 / 512];
        #pragma unroll
        for (int k = 0; k < N2 / 512; ++k) {
            const int i = t + k * 512;
            const float x = xyz2[((size_t)b * N2 + i) * 3 + 0];
            const float y = xyz2[((size_t)b * N2 + i) * 3 + 1];
            const float z = xyz2[((size_t)b * N2 + i) * 3 + 2];
            cl[k] = (cellof(z) << 6) | (cellof(y) << 3) | cellof(x);
            atomicAdd(&cnt[cl[k]], 1);
        }
        __syncthreads();

        sscan[t] = cnt[t];
        __syncthreads();
        #pragma unroll
        for (int off = 1; off < NCELL; off <<= 1) {
            int add = (t >= off) ? sscan[t - off] : 0;
            __syncthreads();
            sscan[t] += add;
            __syncthreads();
        }
        cursor[t] = sscan[t] - cnt[t];
        __syncthreads();

        #pragma unroll
        for (int k = 0; k < N2 / 512; ++k) {
            const int i = t + k * 512;
            const int pos = atomicAdd(&cursor[cl[k]], 1);
            g_qorder[b * N2 + pos] = i;
        }
    }
}

// ---------------------------------------------------------------------------
// Kernel 1: kNN, TWO threads per query (even/odd point split).
// Each half keeps its own sorted top-16; shells expand until
// min(d16_A, d16_B) < (R*h)^2 (safe since merged16 <= min). Final exact
// merge via the bitonic half-cleaner: top16(A u B) = { min(A[i], B[15-i]) }.
// 256 CTAs of 256 thr (128 queries each), cell-sorted query order.
// ---------------------------------------------------------------------------
__global__ __launch_bounds__(256) void knn_kernel(const float* __restrict__ xyz2)
{
    __shared__ float4 spt[N1];            // 32KB
    __shared__ int    cst[NCELL + 1];

    const int b = blockIdx.y;
    for (int i = threadIdx.x; i < N1; i += 256)
        spt[i] = g_sxyz[b * N1 + i];
    for (int i = threadIdx.x; i < NCELL + 1; i += 256)
        cst[i] = g_cellstart[b * (NCELL + 1) + i];
    __syncthreads();

    const int h  = threadIdx.x & 1;                         // half id
    const int qs = blockIdx.x * 128 + (threadIdx.x >> 1);   // sorted idx
    const int qq = g_qorder[b * N2 + qs];
    const size_t qg = (size_t)b * N2 + qq;
    const float qx = xyz2[qg * 3 + 0];
    const float qy = xyz2[qg * 3 + 1];
    const float qz = xyz2[qg * 3 + 2];
    const int cx = cellof(qx), cy = cellof(qy), cz = cellof(qz);

    float dk[NSAMP];
    int   ik[NSAMP];
    #pragma unroll
    for (int p = 0; p < NSAMP; ++p) { dk[p] = 3.4e38f; ik[p] = 0; }

    auto scan_run = [&](int rowbase, int xa, int xb) {
        const int pe = cst[rowbase + xb + 1];
        for (int p = cst[rowbase + xa] + h; p < pe; p += 2) {
            const float4 P = spt[p];
            const float dx = qx - P.x;
            const float dy = qy - P.y;
            const float dz = qz - P.z;
            const float d2 = fmaf(dx, dx, fmaf(dy, dy, dz * dz));
            if (d2 < dk[NSAMP - 1]) {
                dk[NSAMP - 1] = d2;
                ik[NSAMP - 1] = __float_as_int(P.w);
                #pragma unroll
                for (int s = NSAMP - 1; s > 0; --s) {
                    if (dk[s] < dk[s - 1]) {
                        float td = dk[s]; dk[s] = dk[s-1]; dk[s-1] = td;
                        int   ti = ik[s]; ik[s] = ik[s-1]; ik[s-1] = ti;
                    }
                }
            }
        }
    };

    for (int R = 0; R < GRID; ++R) {
        const int zlo = max(cz - R, 0), zhi = min(cz + R, GRID - 1);
        const int ylo = max(cy - R, 0), yhi = min(cy + R, GRID - 1);
        const int xlo = max(cx - R, 0), xhi = min(cx + R, GRID - 1);
        for (int z = zlo; z <= zhi; ++z) {
            const int az = abs(z - cz);
            for (int y = ylo; y <= yhi; ++y) {
                const int ay = abs(y - cy);
                const int rowbase = (z << 6) | (y << 3);
                if (az == R || ay == R) {
                    scan_run(rowbase, xlo, xhi);       // full row in shell
                } else {
                    if (cx - R >= 0)        scan_run(rowbase, cx - R, cx - R);
                    if (cx + R <= GRID - 1) scan_run(rowbase, cx + R, cx + R);
                }
            }
        }
        const float bnd = (float)R * CELLH;
        const float od16 = __shfl_xor_sync(0xffffffffu, dk[NSAMP - 1], 1);
        if (fminf(dk[NSAMP - 1], od16) < bnd * bnd) break;
    }

    // exact merge of the two sorted halves: top16 = { min(A[i], B[15-i]) }
    float pdk[NSAMP];
    int   pik[NSAMP];
    #pragma unroll
    for (int p = 0; p < NSAMP; ++p) {
        pdk[p] = __shfl_xor_sync(0xffffffffu, dk[p], 1);
        pik[p] = __shfl_xor_sync(0xffffffffu, ik[p], 1);
    }
    if (h == 0) {
        int* o = g_idx + qg * NSAMP;
        #pragma unroll
        for (int p = 0; p < NSAMP; ++p)
            o[p] = (dk[p] < pdk[NSAMP - 1 - p]) ? ik[p] : pik[NSAMP - 1 - p];
    }
}

// ---------------------------------------------------------------------------
// Kernel 2: weighted aggregation on TENSOR CORES. (Frozen R16.)
// ---------------------------------------------------------------------------
__global__ __launch_bounds__(128) void wf_kernel(
    const float* __restrict__ xyz1, const float* __restrict__ feat1,
    const float* __restrict__ xyz2, const float* __restrict__ kp)
{
    const int wid = threadIdx.x >> 5;
    const int L   = threadIdx.x & 31;
    const int qi  = blockIdx.x * 4 + wid;    // sorted index
    const int b   = qi >> 13;

    __shared__ float skp[48];                         // KP*3 = 45, pad to 48
    __shared__ float srel[4][NSAMP][4];               // [warp][s][xyz,pad]
    __shared__ int   sq[4];
    __shared__ __align__(256) __half sF[4][NSAMP][C1];  // 4KB per warp

    if (threadIdx.x < 48)
        skp[threadIdx.x] = (threadIdx.x < KP * 3) ? kp[threadIdx.x] : 0.0f;
    if (L == 0) sq[wid] = b * N2 + g_qorder[qi];
    __syncthreads();

    const int q = sq[wid];                    // original query id (global)

    int sid = 0;
    if (L < NSAMP) {
        sid = g_idx[(size_t)q * NSAMP + L];
        srel[wid][L][0] = xyz1[((size_t)b * N1 + sid) * 3 + 0] - xyz2[(size_t)q * 3 + 0];
        srel[wid][L][1] = xyz1[((size_t)b * N1 + sid) * 3 + 1] - xyz2[(size_t)q * 3 + 1];
        srel[wid][L][2] = xyz1[((size_t)b * N1 + sid) * 3 + 2] - xyz2[(size_t)q * 3 + 2];
    }
    __syncwarp();

    const float* fb = feat1 + (size_t)b * N1 * C1;
    char* fB = (char*)&sF[wid][0][0];
    #pragma unroll
    for (int s = 0; s < NSAMP; ++s) {
        const int is = __shfl_sync(0xffffffffu, sid, s);
        const float4 v = *(const float4*)(fb + (size_t)is * C1 + 4 * L);
        __half2 h0 = __floats2half2_rn(v.x, v.y);
        __half2 h1 = __floats2half2_rn(v.z, v.w);
        const int off  = 8 * L;                 // byte offset in 256B row
        const int swq  = (off >> 4) ^ s;        // quad ^ row
        uint2 st;
        st.x = *(const uint32_t*)&h0;
        st.y = *(const uint32_t*)&h1;
        *(uint2*)(fB + s * 256 + (swq << 4) + (off & 15)) = st;
    }

    const int r  = L >> 2;                    // 0..7
    const int c0 = (L & 3) * 2;               // s base 0,2,4,6
    float relv[4][3];
    #pragma unroll
    for (int j = 0; j < 4; ++j) {
        const int s = c0 + (j & 1) + (j >> 1) * 8;   // c0, c0+1, c0+8, c0+9
        relv[j][0] = srel[wid][s][0];
        relv[j][1] = srel[wid][s][1];
        relv[j][2] = srel[wid][s][2];
    }
    uint32_t afr[4];
    #pragma unroll
    for (int hh = 0; hh < 2; ++hh) {
        const int k = r + 8 * hh;             // 0..15 (15 = pad row)
        const float kx = skp[k * 3 + 0];
        const float ky = skp[k * 3 + 1];
        const float kz = skp[k * 3 + 2];
        float w[4];
        #pragma unroll
        for (int j = 0; j < 4; ++j) {
            const float dx = relv[j][0] - kx;
            const float dy = relv[j][1] - ky;
            const float dz = relv[j][2] - kz;
            const float sq2 = dx * dx + dy * dy + dz * dz;
            const float dist = sqrtf(fmaxf(sq2, 1e-12f));
            w[j] = (k == KP) ? 0.0f : fmaxf(0.0f, 1.0f - dist / 0.2f);
        }
        __half2 lo = __floats2half2_rn(w[0], w[1]);
        __half2 hi = __floats2half2_rn(w[2], w[3]);
        afr[hh]     = *(const uint32_t*)&lo;
        afr[2 + hh] = *(const uint32_t*)&hi;
    }
    __syncwarp();   // sF fully written by this warp

    const uint32_t fbase = smem_u32(&sF[wid][0][0]);
    const int rr = L & 15;                    // ldmatrix row provider
    __half* ga = g_a + (size_t)q * KDIM;
    #pragma unroll
    for (int chunk = 0; chunk < 16; ++chunk) {
        uint32_t b0, b1;
        ldsm2t(b0, b1, fbase + rr * 256 + (((chunk ^ rr) & 15) << 4));
        uint32_t bfr[2] = { b0, b1 };
        float d[4] = { 0.0f, 0.0f, 0.0f, 0.0f };
        mma16816h(d, afr, bfr);
        const int nc = chunk * 8 + c0;
        __half2 o0 = __floats2half2_rn(d[0], d[1]);
        *(__half2*)(ga + r * C1 + nc) = o0;
        if (r < 7) {                          // k = r+8 (skip pad row 15)
            __half2 o1 = __floats2half2_rn(d[2], d[3]);
            *(__half2*)(ga + (r + 8) * C1 + nc) = o1;
        }
    }
}

// ---------------------------------------------------------------------------
// Kernel 3: mma.sync pure fp16 GEMM (1 product), fused concat. (Frozen R15.)
// ---------------------------------------------------------------------------
#define A_SUB       8192                // 128 rows x 64B
#define B_SUB       8192                // 128 rows x 64B
#define STAGE_BYTES (A_SUB + B_SUB)           // 16KB
#define NSTAGE      4
#define GEMM_SMEM   (NSTAGE * STAGE_BYTES)    // 64KB

__global__ __launch_bounds__(256, 2)
void gemm_kernel(const float* __restrict__ feat2, float* __restrict__ out)
{
    extern __shared__ __align__(1024) char dsmem[];

    const int tid = threadIdx.x;
    const int wid = tid >> 5;
    const int L   = tid & 31;
    const int m0  = blockIdx.x * 128;
    const int wm  = wid & 1;              // 0..1 (M, 64 rows each)
    const int wn  = wid >> 1;             // 0..3 (N, 32 cols each)

    const uint32_t base = smem_u32(dsmem);

    const char* srcA = (const char*)g_a + (size_t)m0 * (KDIM * 2);
    const char* srcB = (const char*)g_b;

    auto load_stage = [&](int chunk, int buf) {
        const uint32_t sbase = base + buf * STAGE_BYTES;
        #pragma unroll
        for (int v = 0; v < 2; ++v) {
            int idx = v * 256 + tid;          // 0..511
            int row = idx >> 2;               // 0..127
            int kb  = (idx & 3) << 4;         // 0..48
            const char* g = srcA + (size_t)row * (KDIM * 2) + chunk * 64 + kb;
            uint32_t sa = sbase + sw64(row, kb);
            asm volatile("cp.async.cg.shared.global [%0], [%1], 16;"
                         :: "r"(sa), "l"(g));
        }
        #pragma unroll
        for (int v = 0; v < 2; ++v) {
            int idx = v * 256 + tid;          // 0..511
            int row = idx >> 2;               // 0..127
            int kb  = (idx & 3) << 4;
            const char* g = srcB + (size_t)row * (KDIM * 2) + chunk * 64 + kb;
            uint32_t sa = sbase + A_SUB + sw64(row, kb);
            asm volatile("cp.async.cg.shared.global [%0], [%1], 16;"
                         :: "r"(sa), "l"(g));
        }
        asm volatile("cp.async.commit_group;" ::: "memory");
    };

    int aRow = wm * 64 + (L & 15);                  // + mt*16
    int aKb  = (L >> 4) * 16;                       // 0 or 16
    int bRow = wn * 32 + ((L >> 4) << 3) + (L & 7); // + ng*16
    int bKb  = ((L >> 3) & 1) * 16;

    uint32_t aOff[4], aXor[4];
    #pragma unroll
    for (int mt = 0; mt < 4; ++mt) {
        int r = aRow + mt * 16;
        aOff[mt] = r * 64;
        aXor[mt] = ((r >> 1) & 3) << 4;
    }
    uint32_t bOff[2], bXor[2];
    #pragma unroll
    for (int ng = 0; ng < 2; ++ng) {
        int r = bRow + ng * 16;
        bOff[ng] = r * 64;
        bXor[ng] = ((r >> 1) & 3) << 4;
    }

    float acc[4][4][4];
    #pragma unroll
    for (int i = 0; i < 4; ++i)
        #pragma unroll
        for (int j = 0; j < 4; ++j)
            #pragma unroll
            for (int k = 0; k < 4; ++k) acc[i][j][k] = 0.0f;

    load_stage(0, 0);
    load_stage(1, 1);
    load_stage(2, 2);

    // fused concat: copy feat2 rows [m0, m0+128) into out[:,128:192)
    {
        const float* f2 = feat2 + (size_t)m0 * C2;
        float* o2 = out + (size_t)m0 * OUTC + FOUT;
        #pragma unroll
        for (int i = 0; i < 8; ++i) {
            int v = i * 256 + tid;            // 0..2047
            int row = v >> 4;
            int j   = v & 15;
            float4 t = *(const float4*)(f2 + (size_t)row * C2 + j * 4);
            *(float4*)(o2 + (size_t)row * OUTC + j * 4) = t;
        }
    }

    for (int i = 0; i < NCHUNK; ++i) {
        const int buf = i & 3;
        if (i + 2 < NCHUNK)
            asm volatile("cp.async.wait_group 2;" ::: "memory");
        else if (i + 1 < NCHUNK)
            asm volatile("cp.async.wait_group 1;" ::: "memory");
        else
            asm volatile("cp.async.wait_group 0;" ::: "memory");
        __syncthreads();

        const uint32_t sb = base + buf * STAGE_BYTES;
        const uint32_t sA = sb;
        const uint32_t sB = sb + A_SUB;

        #pragma unroll
        for (int ks = 0; ks < 2; ++ks) {
            const uint32_t kA = ks * 32 + aKb;
            const uint32_t kB = ks * 32 + bKb;
            uint32_t a[4][4];
            #pragma unroll
            for (int mt = 0; mt < 4; ++mt)
                ldsm4(a[mt], sA + aOff[mt] + (kA ^ aXor[mt]));
            #pragma unroll
            for (int ng = 0; ng < 2; ++ng) {
                uint32_t bb[4];
                ldsm4(bb, sB + bOff[ng] + (kB ^ bXor[ng]));
                #pragma unroll
                for (int mt = 0; mt < 4; ++mt) {
                    mma16816h(acc[mt][ng * 2 + 0], a[mt], &bb[0]);
                    mma16816h(acc[mt][ng * 2 + 1], a[mt], &bb[2]);
                }
            }
        }

        if (i + 3 < NCHUNK) load_stage(i + 3, (i + 3) & 3);
    }

    #pragma unroll
    for (int mt = 0; mt < 4; ++mt) {
        #pragma unroll
        for (int nt = 0; nt < 4; ++nt) {
            const float* c = acc[mt][nt];
            int row = m0 + wm * 64 + mt * 16 + (L >> 2);
            int col = wn * 32 + nt * 8 + (L & 3) * 2;
            float2 v0, v1;
            v0.x = fmaxf(c[0], 0.0f); v0.y = fmaxf(c[1], 0.0f);
            v1.x = fmaxf(c[2], 0.0f); v1.y = fmaxf(c[3], 0.0f);
            *(float2*)(out + (size_t)row * OUTC + col)       = v0;
            *(float2*)(out + (size_t)(row + 8) * OUTC + col) = v1;
        }
    }
}

// ---------------------------------------------------------------------------
// Launch
// ---------------------------------------------------------------------------
extern "C" void kernel_launch(void* const* d_in, const int* in_sizes, int n_in,
                              void* d_out, int out_size)
{
    const float* xyz1  = (const float*)d_in[0];
    const float* feat1 = (const float*)d_in[1];
    const float* xyz2  = (const float*)d_in[2];
    const float* feat2 = (const float*)d_in[3];
    const float* kp    = (const float*)d_in[4];
    const float* W     = (const float*)d_in[5];
    float* out = (float*)d_out;

    cudaFuncSetAttribute(gemm_kernel,
                         cudaFuncAttributeMaxDynamicSharedMemorySize, GEMM_SMEM);

    prep_kernel<<<2 * BATCH + (KDIM * FOUT) / 512, 512>>>(xyz1, xyz2, W);
    knn_kernel<<<dim3(N2 / 128, BATCH), 256>>>(xyz2);
    wf_kernel<<<NQ / 4, 128>>>(xyz1, feat1, xyz2, kp);
    gemm_kernel<<<NQ / 128, 256, GEMM_SMEM>>>(feat2, out);
}